// round 1
// baseline (speedup 1.0000x reference)
#include <cuda_runtime.h>
#include <cuda_bf16.h>
#include <cstdint>
#include <cstdio>

// Problem shape (fixed by the dataset)
#define NN   30000
#define EE   480000
#define INX  3000
#define INR  2048
#define NH   256
#define OUTD 64
#define D2   (2*NH)   // 512

// ---------------- scratch (device globals; no allocs allowed) ----------------
__device__ float    g_H1x [(size_t)NN*NH];   // features @ W1x
__device__ float    g_H1r [(size_t)NN*NH];   // im_features @ W1r
__device__ float    g_Hgx [(size_t)NN*NH];   // gathered (perm) variants
__device__ float    g_Hgr [(size_t)NN*NH];
__device__ float    g_t   [(size_t)NN*D2];   // concat buffer / encode agg target
__device__ float    g_hdec[(size_t)NN*D2];   // h2 @ W2^T
__device__ float    g_h3  [(size_t)NN*D2];   // decode agg target
__device__ float    g_es  [NN];
__device__ float    g_ed  [NN];
__device__ unsigned g_mx  [NN];
__device__ float    g_sum [NN];
__device__ float    g_e   [EE];

// ---------------- tiled SGEMM: C[M,N] = A[M,K] @ (B or B^T) ----------------
#define BM 64
#define BN 64
#define BK 16

template<bool TB>
__global__ void sgemm_kernel(const float* __restrict__ A, const float* __restrict__ B,
                             float* __restrict__ C, int M, int N, int K,
                             int lda, int ldb, int ldc) {
    __shared__ float As[BK][BM + 1];
    __shared__ float Bs[BK][BN + 1];
    const int tid = threadIdx.x;          // 256 threads
    const int bm = blockIdx.y * BM;
    const int bn = blockIdx.x * BN;
    const int tx = tid & 15;              // 16 x 16 thread grid, 4x4 per thread
    const int ty = tid >> 4;

    float acc[4][4] = {};

    const int arow = tid >> 2;            // 0..63
    const int acol = (tid & 3) * 4;       // 0,4,8,12

    for (int k0 = 0; k0 < K; k0 += BK) {
        // A tile: BM x BK, stored transposed
        #pragma unroll
        for (int i = 0; i < 4; i++) {
            int m = bm + arow, k = k0 + acol + i;
            As[acol + i][arow] = (m < M && k < K) ? A[(size_t)m * lda + k] : 0.f;
        }
        if (!TB) {
            const int brow = tid >> 4;        // 0..15 (k)
            const int bcol = (tid & 15) * 4;  // 0..60 (n)
            #pragma unroll
            for (int i = 0; i < 4; i++) {
                int k = k0 + brow, n = bn + bcol + i;
                Bs[brow][bcol + i] = (k < K && n < N) ? B[(size_t)k * ldb + n] : 0.f;
            }
        } else {
            const int brow = tid >> 2;        // 0..63 (n)
            const int bcol = (tid & 3) * 4;   // 0..12 (k)
            #pragma unroll
            for (int i = 0; i < 4; i++) {
                int n = bn + brow, k = k0 + bcol + i;
                Bs[bcol + i][brow] = (n < N && k < K) ? B[(size_t)n * ldb + k] : 0.f;
            }
        }
        __syncthreads();

        #pragma unroll
        for (int kk = 0; kk < BK; kk++) {
            float a[4], b[4];
            #pragma unroll
            for (int i = 0; i < 4; i++) a[i] = As[kk][ty * 4 + i];
            #pragma unroll
            for (int j = 0; j < 4; j++) b[j] = Bs[kk][tx * 4 + j];
            #pragma unroll
            for (int i = 0; i < 4; i++)
                #pragma unroll
                for (int j = 0; j < 4; j++)
                    acc[i][j] += a[i] * b[j];
        }
        __syncthreads();
    }

    #pragma unroll
    for (int i = 0; i < 4; i++) {
        int m = bm + ty * 4 + i;
        if (m >= M) continue;
        #pragma unroll
        for (int j = 0; j < 4; j++) {
            int n = bn + tx * 4 + j;
            if (n < N) C[(size_t)m * ldc + n] = acc[i][j];
        }
    }
}

static void sgemm(const float* A, const float* B, float* C,
                  int M, int N, int K, int lda, int ldb, int ldc, bool transB) {
    dim3 grid((N + BN - 1) / BN, (M + BM - 1) / BM);
    if (transB) sgemm_kernel<true ><<<grid, 256>>>(A, B, C, M, N, K, lda, ldb, ldc);
    else        sgemm_kernel<false><<<grid, 256>>>(A, B, C, M, N, K, lda, ldb, ldc);
}

// ---------------- GAT attention pieces ----------------

// monotone float<->uint mapping for atomicMax on floats
__device__ __forceinline__ unsigned encf(float f) {
    unsigned u = __float_as_uint(f);
    return (u & 0x80000000u) ? ~u : (u | 0x80000000u);
}
__device__ __forceinline__ float decf(unsigned u) {
    return (u & 0x80000000u) ? __uint_as_float(u & 0x7fffffffu) : __uint_as_float(~u);
}

// per-node dot products with attention vectors (warp per node)
__global__ void node_dots_kernel(const float* __restrict__ H,
                                 const float* __restrict__ a_src,
                                 const float* __restrict__ a_dst,
                                 float* __restrict__ es, float* __restrict__ ed,
                                 int N, int D) {
    int warp = (blockIdx.x * blockDim.x + threadIdx.x) >> 5;
    int lane = threadIdx.x & 31;
    if (warp >= N) return;
    const float* row = H + (size_t)warp * D;
    float s1 = 0.f, s2 = 0.f;
    for (int j = lane; j < D; j += 32) {
        float v = row[j];
        s1 += v * a_src[j];
        s2 += v * a_dst[j];
    }
    #pragma unroll
    for (int o = 16; o; o >>= 1) {
        s1 += __shfl_down_sync(0xffffffffu, s1, o);
        s2 += __shfl_down_sync(0xffffffffu, s2, o);
    }
    if (lane == 0) { es[warp] = s1; ed[warp] = s2; }
}

__global__ void edge_logits_kernel(const int* __restrict__ src, const int* __restrict__ dst,
                                   const float* __restrict__ es, const float* __restrict__ ed,
                                   float* __restrict__ ebuf, unsigned* __restrict__ mx, int E) {
    int e = blockIdx.x * blockDim.x + threadIdx.x;
    if (e >= E) return;
    float v = es[src[e]] + ed[dst[e]];
    v = v > 0.f ? v : 0.2f * v;          // leaky_relu(0.2)
    ebuf[e] = v;
    atomicMax(&mx[dst[e]], encf(v));
}

__global__ void edge_exp_kernel(const int* __restrict__ dst,
                                float* __restrict__ ebuf, const unsigned* __restrict__ mx,
                                float* __restrict__ sum, int E) {
    int e = blockIdx.x * blockDim.x + threadIdx.x;
    if (e >= E) return;
    int d = dst[e];
    unsigned u = mx[d];
    float m = (u == 0u) ? 0.f : decf(u);
    float ex = expf(ebuf[e] - m);
    ebuf[e] = ex;
    atomicAdd(&sum[d], ex);
}

// warp per edge: out[dst] += alpha * H[src]
__global__ void edge_agg_kernel(const int* __restrict__ src, const int* __restrict__ dst,
                                const float* __restrict__ H, const float* __restrict__ ebuf,
                                const float* __restrict__ sum, float* __restrict__ out,
                                int E, int D, int ldo) {
    int warp = (blockIdx.x * blockDim.x + threadIdx.x) >> 5;
    int lane = threadIdx.x & 31;
    if (warp >= E) return;
    int s = src[warp], d = dst[warp];
    float alpha = ebuf[warp] / (sum[d] + 1e-16f);
    const float4* hrow = (const float4*)(H + (size_t)s * D);
    float4*       orow = (float4*)(out + (size_t)d * ldo);
    int nv = D >> 2;
    for (int j = lane; j < nv; j += 32) {
        float4 v = hrow[j];
        v.x *= alpha; v.y *= alpha; v.z *= alpha; v.w *= alpha;
        atomicAdd(&orow[j], v);
    }
}

__global__ void elu_kernel(float* __restrict__ x, size_t n) {
    size_t i = (size_t)blockIdx.x * blockDim.x + threadIdx.x;
    if (i >= n) return;
    float v = x[i];
    x[i] = v > 0.f ? v : expm1f(v);
}

__global__ void gather_rows_kernel(const float* __restrict__ in, const int* __restrict__ perm,
                                   float* __restrict__ out, int N, int D) {
    size_t i = (size_t)blockIdx.x * blockDim.x + threadIdx.x;
    if (i >= (size_t)N * D) return;
    int r = (int)(i / D);
    int c = (int)(i - (size_t)r * D);
    out[i] = in[(size_t)perm[r] * D + c];
}

__global__ void summary_kernel(const float* __restrict__ h2, float* __restrict__ out, int N) {
    int c = blockIdx.x;                 // 64 columns
    __shared__ float sm[256];
    float s = 0.f;
    for (int i = threadIdx.x; i < N; i += blockDim.x)
        s += h2[(size_t)i * OUTD + c];
    sm[threadIdx.x] = s;
    __syncthreads();
    for (int o = 128; o; o >>= 1) {
        if (threadIdx.x < o) sm[threadIdx.x] += sm[threadIdx.x + o];
        __syncthreads();
    }
    if (threadIdx.x == 0) {
        float m = sm[0] / (float)N;
        out[c] = 1.f / (1.f + expf(-m));
    }
}

// ---------------- host orchestration ----------------

static void run_gat(const float* H, int D,
                    const float* a_src, const float* a_dst,
                    const int* src, const int* dst,
                    float* es, float* ed, unsigned* mx, float* sum, float* ebuf,
                    float* out, int ldo) {
    cudaMemsetAsync(mx, 0, NN * sizeof(unsigned));
    cudaMemsetAsync(sum, 0, NN * sizeof(float));
    node_dots_kernel<<<(NN * 32 + 255) / 256, 256>>>(H, a_src, a_dst, es, ed, NN, D);
    edge_logits_kernel<<<(EE + 255) / 256, 256>>>(src, dst, es, ed, ebuf, mx, EE);
    edge_exp_kernel<<<(EE + 255) / 256, 256>>>(dst, ebuf, mx, sum, EE);
    edge_agg_kernel<<<(EE * 32 + 255) / 256, 256>>>(src, dst, H, ebuf, sum, out, EE, D, ldo);
}

extern "C" void kernel_launch(void* const* d_in, const int* in_sizes, int n_in,
                              void* d_out, int out_size) {
    const float* features    = (const float*)d_in[0];
    const float* im_features = (const float*)d_in[1];
    const float* W1x         = (const float*)d_in[2];
    const float* a1x_src     = (const float*)d_in[3];
    const float* a1x_dst     = (const float*)d_in[4];
    const float* W1r         = (const float*)d_in[5];
    const float* a1r_src     = (const float*)d_in[6];
    const float* a1r_dst     = (const float*)d_in[7];
    const float* W2          = (const float*)d_in[8];
    const float* a3_src      = (const float*)d_in[9];
    const float* a3_dst      = (const float*)d_in[10];
    const int*   edge_index  = (const int*)d_in[11];
    const int*   perm        = (const int*)d_in[12];

    const int* src = edge_index;
    const int* dst = edge_index + EE;

    void* p;
    cudaGetSymbolAddress(&p, g_H1x);  float* H1x  = (float*)p;
    cudaGetSymbolAddress(&p, g_H1r);  float* H1r  = (float*)p;
    cudaGetSymbolAddress(&p, g_Hgx);  float* Hgx  = (float*)p;
    cudaGetSymbolAddress(&p, g_Hgr);  float* Hgr  = (float*)p;
    cudaGetSymbolAddress(&p, g_t);    float* tbuf = (float*)p;
    cudaGetSymbolAddress(&p, g_hdec); float* hdec = (float*)p;
    cudaGetSymbolAddress(&p, g_h3);   float* h3   = (float*)p;
    cudaGetSymbolAddress(&p, g_es);   float* es   = (float*)p;
    cudaGetSymbolAddress(&p, g_ed);   float* ed   = (float*)p;
    cudaGetSymbolAddress(&p, g_mx);   unsigned* mx = (unsigned*)p;
    cudaGetSymbolAddress(&p, g_sum);  float* sumb = (float*)p;
    cudaGetSymbolAddress(&p, g_e);    float* ebuf = (float*)p;

    float* out = (float*)d_out;
    const size_t S_h2  = (size_t)NN * OUTD;
    const size_t S_h4x = (size_t)NN * INX;
    const size_t S_h4r = (size_t)NN * INR;
    const size_t passSz = S_h2 + S_h4x + S_h4r;

    // Big input GEMMs once; permuted pass reuses rows via gather.
    sgemm(features,    W1x, H1x, NN, NH, INX, INX, NH, NH, false);
    sgemm(im_features, W1r, H1r, NN, NH, INR, INR, NH, NH, false);

    for (int pass = 0; pass < 2; pass++) {
        const float* Hx = H1x;
        const float* Hr = H1r;
        if (pass) {
            size_t n = (size_t)NN * NH;
            gather_rows_kernel<<<(unsigned)((n + 255) / 256), 256>>>(H1x, perm, Hgx, NN, NH);
            gather_rows_kernel<<<(unsigned)((n + 255) / 256), 256>>>(H1r, perm, Hgr, NN, NH);
            Hx = Hgx; Hr = Hgr;
        }

        // encode: two GATs into the halves of t, then elu
        cudaMemsetAsync(tbuf, 0, (size_t)NN * D2 * sizeof(float));
        run_gat(Hx, NH, a1x_src, a1x_dst, src, dst, es, ed, mx, sumb, ebuf, tbuf,       D2);
        run_gat(Hr, NH, a1r_src, a1r_dst, src, dst, es, ed, mx, sumb, ebuf, tbuf + NH,  D2);
        {
            size_t n = (size_t)NN * D2;
            elu_kernel<<<(unsigned)((n + 255) / 256), 256>>>(tbuf, n);
        }

        float* h2  = out + (size_t)pass * passSz;
        float* h4x = h2 + S_h2;
        float* h4r = h4x + S_h4x;

        // h2 = t @ W2
        sgemm(tbuf, W2, h2, NN, OUTD, D2, D2, OUTD, OUTD, false);

        // decode: h = h2 @ W2^T
        sgemm(h2, W2, hdec, NN, D2, OUTD, OUTD, OUTD, D2, true);

        cudaMemsetAsync(h3, 0, (size_t)NN * D2 * sizeof(float));
        run_gat(hdec, D2, a3_src, a3_dst, src, dst, es, ed, mx, sumb, ebuf, h3, D2);
        {
            size_t n = (size_t)NN * D2;
            elu_kernel<<<(unsigned)((n + 255) / 256), 256>>>(h3, n);
        }

        // h4x = h3[:, :256] @ W1x^T ; h4r = h3[:, 256:] @ W1r^T
        sgemm(h3,      W1x, h4x, NN, INX, NH, D2, NH, INX, true);
        sgemm(h3 + NH, W1r, h4r, NN, INR, NH, D2, NH, INR, true);
    }

    // summary = sigmoid(mean(h2_orig, axis=0))
    summary_kernel<<<OUTD, 256>>>(out, out + 2 * passSz, NN);
}

// round 2
// speedup vs baseline: 1.7169x; 1.7169x over previous
#include <cuda_runtime.h>
#include <cuda_bf16.h>
#include <cstdint>
#include <cstdio>

// Problem shape (fixed by the dataset)
#define NN   30000
#define EE   480000
#define INX  3000
#define INR  2048
#define NH   256
#define OUTD 64
#define D2   (2*NH)   // 512

// ---------------- scratch (device globals; no allocs allowed) ----------------
__device__ float    g_H1x [(size_t)NN*NH];   // features @ W1x
__device__ float    g_H1r [(size_t)NN*NH];   // im_features @ W1r
__device__ float    g_Hgx [(size_t)NN*NH];   // gathered (perm) variants
__device__ float    g_Hgr [(size_t)NN*NH];
__device__ float    g_t   [(size_t)NN*D2];   // concat buffer / encode agg target
__device__ float    g_hdec[(size_t)NN*D2];   // h2 @ W2^T
__device__ float    g_h3  [(size_t)NN*D2];   // decode agg target
__device__ float    g_es  [NN];
__device__ float    g_ed  [NN];
__device__ unsigned g_mx  [NN];
__device__ float    g_sum [NN];
__device__ float    g_e   [EE];

// ---------------- 128x128x16 double-buffered SGEMM ----------------
// C[M,N] = A[M,K] @ B        (TB=false, B is K x N, ldb = N-stride)
// C[M,N] = A[M,K] @ B^T      (TB=true,  B is N x K, ldb = K-stride)
#define TBM 128
#define TBN 128
#define TBK 16

template<bool TB>
__global__ __launch_bounds__(256, 2)
void sgemm_tile(const float* __restrict__ A, const float* __restrict__ B,
                float* __restrict__ C, int M, int N, int K,
                int lda, int ldb, int ldc) {
    __shared__ float As[2][TBK][TBM];
    __shared__ float Bs[2][TBK][TBN];

    const int tid = threadIdx.x;
    const int bm = blockIdx.y * TBM;
    const int bn = blockIdx.x * TBN;
    const int tx = tid & 15;
    const int ty = tid >> 4;

    // A-load mapping: each thread 2 float4 along K
    const int a_m = tid >> 2;          // 0..63
    const int a_k = (tid & 3) * 4;     // 0,4,8,12

    float4 pa[2], pb[2];
    float acc[8][8] = {};

    auto loadA = [&](int k0) {
        #pragma unroll
        for (int h = 0; h < 2; h++) {
            int m = bm + a_m + h * 64;
            int k = k0 + a_k;
            float4 v = {0.f, 0.f, 0.f, 0.f};
            if (m < M) {
                const float* p = A + (size_t)m * lda + k;
                if (k + 3 < K) v = *(const float4*)p;
                else {
                    if (k + 0 < K) v.x = p[0];
                    if (k + 1 < K) v.y = p[1];
                    if (k + 2 < K) v.z = p[2];
                }
            }
            pa[h] = v;
        }
    };
    auto loadB = [&](int k0) {
        if (!TB) {
            int kk = tid >> 5, n = (tid & 31) * 4;
            #pragma unroll
            for (int h = 0; h < 2; h++) {
                int k = k0 + kk + h * 8;
                int nn = bn + n;
                float4 v = {0.f, 0.f, 0.f, 0.f};
                if (k < K) {
                    const float* p = B + (size_t)k * ldb + nn;
                    if (nn + 3 < N) v = *(const float4*)p;
                    else {
                        if (nn + 0 < N) v.x = p[0];
                        if (nn + 1 < N) v.y = p[1];
                        if (nn + 2 < N) v.z = p[2];
                    }
                }
                pb[h] = v;
            }
        } else {
            int n = tid >> 2, k4 = (tid & 3) * 4;
            #pragma unroll
            for (int h = 0; h < 2; h++) {
                int nn = bn + n + h * 64;
                int k = k0 + k4;
                float4 v = {0.f, 0.f, 0.f, 0.f};
                if (nn < N) {
                    const float* p = B + (size_t)nn * ldb + k;
                    if (k + 3 < K) v = *(const float4*)p;
                    else {
                        if (k + 0 < K) v.x = p[0];
                        if (k + 1 < K) v.y = p[1];
                        if (k + 2 < K) v.z = p[2];
                    }
                }
                pb[h] = v;
            }
        }
    };
    auto stageA = [&](int buf) {
        #pragma unroll
        for (int h = 0; h < 2; h++) {
            int m = a_m + h * 64;
            As[buf][a_k + 0][m] = pa[h].x;
            As[buf][a_k + 1][m] = pa[h].y;
            As[buf][a_k + 2][m] = pa[h].z;
            As[buf][a_k + 3][m] = pa[h].w;
        }
    };
    auto stageB = [&](int buf) {
        if (!TB) {
            int kk = tid >> 5, n = (tid & 31) * 4;
            #pragma unroll
            for (int h = 0; h < 2; h++)
                *(float4*)&Bs[buf][kk + h * 8][n] = pb[h];
        } else {
            int n = tid >> 2, k4 = (tid & 3) * 4;
            #pragma unroll
            for (int h = 0; h < 2; h++) {
                int nn = n + h * 64;
                Bs[buf][k4 + 0][nn] = pb[h].x;
                Bs[buf][k4 + 1][nn] = pb[h].y;
                Bs[buf][k4 + 2][nn] = pb[h].z;
                Bs[buf][k4 + 3][nn] = pb[h].w;
            }
        }
    };

    loadA(0); loadB(0);
    stageA(0); stageB(0);
    __syncthreads();

    const int nk = (K + TBK - 1) / TBK;
    int buf = 0;
    for (int t = 0; t < nk; t++) {
        bool more = (t + 1 < nk);
        if (more) { loadA((t + 1) * TBK); loadB((t + 1) * TBK); }

        #pragma unroll
        for (int kk = 0; kk < TBK; kk++) {
            float4 a0 = *(const float4*)&As[buf][kk][ty * 4];
            float4 a1 = *(const float4*)&As[buf][kk][64 + ty * 4];
            float4 b0 = *(const float4*)&Bs[buf][kk][tx * 4];
            float4 b1 = *(const float4*)&Bs[buf][kk][64 + tx * 4];
            float av[8] = {a0.x, a0.y, a0.z, a0.w, a1.x, a1.y, a1.z, a1.w};
            float bv[8] = {b0.x, b0.y, b0.z, b0.w, b1.x, b1.y, b1.z, b1.w};
            #pragma unroll
            for (int i = 0; i < 8; i++)
                #pragma unroll
                for (int j = 0; j < 8; j++)
                    acc[i][j] += av[i] * bv[j];
        }
        if (more) {
            stageA(buf ^ 1); stageB(buf ^ 1);
            __syncthreads();
            buf ^= 1;
        }
    }

    // epilogue
    #pragma unroll
    for (int i = 0; i < 8; i++) {
        int m = bm + (i < 4 ? ty * 4 + i : 64 + ty * 4 + (i - 4));
        if (m >= M) continue;
        #pragma unroll
        for (int j = 0; j < 8; j++) {
            int n = bn + (j < 4 ? tx * 4 + j : 64 + tx * 4 + (j - 4));
            if (n < N) C[(size_t)m * ldc + n] = acc[i][j];
        }
    }
}

static void sgemm(const float* A, const float* B, float* C,
                  int M, int N, int K, int lda, int ldb, int ldc, bool transB) {
    dim3 grid((N + TBN - 1) / TBN, (M + TBM - 1) / TBM);
    if (transB) sgemm_tile<true ><<<grid, 256>>>(A, B, C, M, N, K, lda, ldb, ldc);
    else        sgemm_tile<false><<<grid, 256>>>(A, B, C, M, N, K, lda, ldb, ldc);
}

// ---------------- GAT attention pieces ----------------

__device__ __forceinline__ unsigned encf(float f) {
    unsigned u = __float_as_uint(f);
    return (u & 0x80000000u) ? ~u : (u | 0x80000000u);
}
__device__ __forceinline__ float decf(unsigned u) {
    return (u & 0x80000000u) ? __uint_as_float(u & 0x7fffffffu) : __uint_as_float(~u);
}

__global__ void node_dots_kernel(const float* __restrict__ H,
                                 const float* __restrict__ a_src,
                                 const float* __restrict__ a_dst,
                                 float* __restrict__ es, float* __restrict__ ed,
                                 int N, int D) {
    int warp = (blockIdx.x * blockDim.x + threadIdx.x) >> 5;
    int lane = threadIdx.x & 31;
    if (warp >= N) return;
    const float* row = H + (size_t)warp * D;
    float s1 = 0.f, s2 = 0.f;
    for (int j = lane; j < D; j += 32) {
        float v = row[j];
        s1 += v * a_src[j];
        s2 += v * a_dst[j];
    }
    #pragma unroll
    for (int o = 16; o; o >>= 1) {
        s1 += __shfl_down_sync(0xffffffffu, s1, o);
        s2 += __shfl_down_sync(0xffffffffu, s2, o);
    }
    if (lane == 0) { es[warp] = s1; ed[warp] = s2; }
}

__global__ void edge_logits_kernel(const int* __restrict__ src, const int* __restrict__ dst,
                                   const float* __restrict__ es, const float* __restrict__ ed,
                                   float* __restrict__ ebuf, unsigned* __restrict__ mx, int E) {
    int e = blockIdx.x * blockDim.x + threadIdx.x;
    if (e >= E) return;
    float v = es[src[e]] + ed[dst[e]];
    v = v > 0.f ? v : 0.2f * v;
    ebuf[e] = v;
    atomicMax(&mx[dst[e]], encf(v));
}

__global__ void edge_exp_kernel(const int* __restrict__ dst,
                                float* __restrict__ ebuf, const unsigned* __restrict__ mx,
                                float* __restrict__ sum, int E) {
    int e = blockIdx.x * blockDim.x + threadIdx.x;
    if (e >= E) return;
    int d = dst[e];
    unsigned u = mx[d];
    float m = (u == 0u) ? 0.f : decf(u);
    float ex = expf(ebuf[e] - m);
    ebuf[e] = ex;
    atomicAdd(&sum[d], ex);
}

__global__ void edge_agg_kernel(const int* __restrict__ src, const int* __restrict__ dst,
                                const float* __restrict__ H, const float* __restrict__ ebuf,
                                const float* __restrict__ sum, float* __restrict__ out,
                                int E, int D, int ldo) {
    int warp = (blockIdx.x * blockDim.x + threadIdx.x) >> 5;
    int lane = threadIdx.x & 31;
    if (warp >= E) return;
    int s = src[warp], d = dst[warp];
    float alpha = ebuf[warp] / (sum[d] + 1e-16f);
    const float4* hrow = (const float4*)(H + (size_t)s * D);
    float4*       orow = (float4*)(out + (size_t)d * ldo);
    int nv = D >> 2;
    for (int j = lane; j < nv; j += 32) {
        float4 v = hrow[j];
        v.x *= alpha; v.y *= alpha; v.z *= alpha; v.w *= alpha;
        atomicAdd(&orow[j], v);
    }
}

__global__ void elu_kernel(float* __restrict__ x, size_t n) {
    size_t i = (size_t)blockIdx.x * blockDim.x + threadIdx.x;
    if (i >= n) return;
    float v = x[i];
    x[i] = v > 0.f ? v : expm1f(v);
}

// float4 row gather: out[r] = in[perm[r]]
__global__ void gather_rows4_kernel(const float4* __restrict__ in, const int* __restrict__ perm,
                                    float4* __restrict__ out, int N, int Dv) {
    size_t i = (size_t)blockIdx.x * blockDim.x + threadIdx.x;
    if (i >= (size_t)N * Dv) return;
    int r = (int)(i / Dv);
    int c = (int)(i - (size_t)r * Dv);
    out[i] = in[(size_t)perm[r] * Dv + c];
}

__global__ void summary_kernel(const float* __restrict__ h2, float* __restrict__ out, int N) {
    int c = blockIdx.x;
    __shared__ float sm[256];
    float s = 0.f;
    for (int i = threadIdx.x; i < N; i += blockDim.x)
        s += h2[(size_t)i * OUTD + c];
    sm[threadIdx.x] = s;
    __syncthreads();
    for (int o = 128; o; o >>= 1) {
        if (threadIdx.x < o) sm[threadIdx.x] += sm[threadIdx.x + o];
        __syncthreads();
    }
    if (threadIdx.x == 0) {
        float m = sm[0] / (float)N;
        out[c] = 1.f / (1.f + expf(-m));
    }
}

// ---------------- host orchestration ----------------

static void run_gat(const float* H, int D,
                    const float* a_src, const float* a_dst,
                    const int* src, const int* dst,
                    float* es, float* ed, unsigned* mx, float* sum, float* ebuf,
                    float* out, int ldo) {
    cudaMemsetAsync(mx, 0, NN * sizeof(unsigned));
    cudaMemsetAsync(sum, 0, NN * sizeof(float));
    node_dots_kernel<<<(NN * 32 + 255) / 256, 256>>>(H, a_src, a_dst, es, ed, NN, D);
    edge_logits_kernel<<<(EE + 255) / 256, 256>>>(src, dst, es, ed, ebuf, mx, EE);
    edge_exp_kernel<<<(EE + 255) / 256, 256>>>(dst, ebuf, mx, sum, EE);
    edge_agg_kernel<<<(EE * 32 + 255) / 256, 256>>>(src, dst, H, ebuf, sum, out, EE, D, ldo);
}

extern "C" void kernel_launch(void* const* d_in, const int* in_sizes, int n_in,
                              void* d_out, int out_size) {
    const float* features    = (const float*)d_in[0];
    const float* im_features = (const float*)d_in[1];
    const float* W1x         = (const float*)d_in[2];
    const float* a1x_src     = (const float*)d_in[3];
    const float* a1x_dst     = (const float*)d_in[4];
    const float* W1r         = (const float*)d_in[5];
    const float* a1r_src     = (const float*)d_in[6];
    const float* a1r_dst     = (const float*)d_in[7];
    const float* W2          = (const float*)d_in[8];
    const float* a3_src      = (const float*)d_in[9];
    const float* a3_dst      = (const float*)d_in[10];
    const int*   edge_index  = (const int*)d_in[11];
    const int*   perm        = (const int*)d_in[12];

    const int* src = edge_index;
    const int* dst = edge_index + EE;

    void* p;
    cudaGetSymbolAddress(&p, g_H1x);  float* H1x  = (float*)p;
    cudaGetSymbolAddress(&p, g_H1r);  float* H1r  = (float*)p;
    cudaGetSymbolAddress(&p, g_Hgx);  float* Hgx  = (float*)p;
    cudaGetSymbolAddress(&p, g_Hgr);  float* Hgr  = (float*)p;
    cudaGetSymbolAddress(&p, g_t);    float* tbuf = (float*)p;
    cudaGetSymbolAddress(&p, g_hdec); float* hdec = (float*)p;
    cudaGetSymbolAddress(&p, g_h3);   float* h3   = (float*)p;
    cudaGetSymbolAddress(&p, g_es);   float* es   = (float*)p;
    cudaGetSymbolAddress(&p, g_ed);   float* ed   = (float*)p;
    cudaGetSymbolAddress(&p, g_mx);   unsigned* mx = (unsigned*)p;
    cudaGetSymbolAddress(&p, g_sum);  float* sumb = (float*)p;
    cudaGetSymbolAddress(&p, g_e);    float* ebuf = (float*)p;

    float* out = (float*)d_out;
    const size_t S_h2  = (size_t)NN * OUTD;
    const size_t S_h4x = (size_t)NN * INX;
    const size_t S_h4r = (size_t)NN * INR;
    const size_t passSz = S_h2 + S_h4x + S_h4r;

    // Big input GEMMs once; permuted pass reuses rows via gather.
    sgemm(features,    W1x, H1x, NN, NH, INX, INX, NH, NH, false);
    sgemm(im_features, W1r, H1r, NN, NH, INR, INR, NH, NH, false);

    for (int pass = 0; pass < 2; pass++) {
        const float* Hx = H1x;
        const float* Hr = H1r;
        if (pass) {
            size_t n4 = (size_t)NN * (NH / 4);
            gather_rows4_kernel<<<(unsigned)((n4 + 255) / 256), 256>>>((const float4*)H1x, perm, (float4*)Hgx, NN, NH / 4);
            gather_rows4_kernel<<<(unsigned)((n4 + 255) / 256), 256>>>((const float4*)H1r, perm, (float4*)Hgr, NN, NH / 4);
            Hx = Hgx; Hr = Hgr;
        }

        cudaMemsetAsync(tbuf, 0, (size_t)NN * D2 * sizeof(float));
        run_gat(Hx, NH, a1x_src, a1x_dst, src, dst, es, ed, mx, sumb, ebuf, tbuf,      D2);
        run_gat(Hr, NH, a1r_src, a1r_dst, src, dst, es, ed, mx, sumb, ebuf, tbuf + NH, D2);
        {
            size_t n = (size_t)NN * D2;
            elu_kernel<<<(unsigned)((n + 255) / 256), 256>>>(tbuf, n);
        }

        float* h2  = out + (size_t)pass * passSz;
        float* h4x = h2 + S_h2;
        float* h4r = h4x + S_h4x;

        sgemm(tbuf, W2, h2, NN, OUTD, D2, D2, OUTD, OUTD, false);
        sgemm(h2, W2, hdec, NN, D2, OUTD, OUTD, OUTD, D2, true);

        cudaMemsetAsync(h3, 0, (size_t)NN * D2 * sizeof(float));
        run_gat(hdec, D2, a3_src, a3_dst, src, dst, es, ed, mx, sumb, ebuf, h3, D2);
        {
            size_t n = (size_t)NN * D2;
            elu_kernel<<<(unsigned)((n + 255) / 256), 256>>>(h3, n);
        }

        sgemm(h3,      W1x, h4x, NN, INX, NH, D2, NH, INX, true);
        sgemm(h3 + NH, W1r, h4r, NN, INR, NH, D2, NH, INR, true);
    }

    summary_kernel<<<OUTD, 256>>>(out, out + 2 * passSz, NN);
}

// round 3
// speedup vs baseline: 2.6536x; 1.5455x over previous
#include <cuda_runtime.h>
#include <cuda_bf16.h>
#include <cstdint>
#include <cstdio>

// Problem shape (fixed by the dataset)
#define NN   30000
#define EE   480000
#define INX  3000
#define INR  2048
#define NH   256
#define OUTD 64
#define D2   (2*NH)   // 512

// ---------------- scratch (device globals; no allocs allowed) ----------------
__device__ float    g_H1x [(size_t)NN*NH];
__device__ float    g_H1r [(size_t)NN*NH];
__device__ float    g_Hgx [(size_t)NN*NH];
__device__ float    g_Hgr [(size_t)NN*NH];
__device__ float    g_t   [(size_t)NN*D2];
__device__ float    g_hdec[(size_t)NN*D2];
__device__ float    g_h3  [(size_t)NN*D2];
__device__ float    g_es  [NN];
__device__ float    g_ed  [NN];
__device__ unsigned g_mx  [NN];
__device__ float    g_sum [NN];
__device__ float    g_e   [EE];

// ---------------- TF32 tensor-core GEMM ----------------
// C[M,N] = A[M,K] @ B      (TB=false, B is K x N)
// C[M,N] = A[M,K] @ B^T    (TB=true,  B is N x K)
// Block tile 128x128x16, 8 warps (4 along M, 2 along N), warp tile 32x64,
// mma.sync.aligned.m16n8k8.row.col.f32.tf32.tf32.f32

#define GBM 128
#define GBN 128
#define GBK 16
#define AS_STRIDE 20    // 16 + 4 pad: conflict-free A fragment loads
#define BS_STRIDE 132   // 128 + 4 pad

__device__ __forceinline__ unsigned f2tf32(float f) {
    unsigned r;
    asm("cvt.rna.tf32.f32 %0, %1;" : "=r"(r) : "f"(f));
    return r;
}

__device__ __forceinline__ void mma_tf32(float c[4],
                                         unsigned a0, unsigned a1, unsigned a2, unsigned a3,
                                         unsigned b0, unsigned b1) {
    asm volatile(
        "mma.sync.aligned.m16n8k8.row.col.f32.tf32.tf32.f32 "
        "{%0,%1,%2,%3}, {%4,%5,%6,%7}, {%8,%9}, {%0,%1,%2,%3};"
        : "+f"(c[0]), "+f"(c[1]), "+f"(c[2]), "+f"(c[3])
        : "r"(a0), "r"(a1), "r"(a2), "r"(a3), "r"(b0), "r"(b1));
}

template<bool TB>
__global__ __launch_bounds__(256)
void tf32_gemm(const float* __restrict__ A, const float* __restrict__ B,
               float* __restrict__ C, int M, int N, int K,
               int lda, int ldb, int ldc) {
    __shared__ unsigned As[2][GBM][AS_STRIDE];   // [m][k]
    __shared__ unsigned Bs[2][GBK][BS_STRIDE];   // [k][n]

    const int tid  = threadIdx.x;
    const int lane = tid & 31;
    const int wid  = tid >> 5;
    const int wm   = wid & 3;        // 0..3  -> 32-row slab
    const int wn   = wid >> 2;       // 0..1  -> 64-col slab
    const int bm   = blockIdx.y * GBM;
    const int bn   = blockIdx.x * GBN;

    const int grp  = lane >> 2;      // 0..7
    const int tig  = lane & 3;       // 0..3

    // staging register buffers
    unsigned sa[2][4];               // 2 float4 of A per thread
    unsigned sb[2][4];
    // A staging map: row = tid>>1 (0..127), k = (tid&1)*8 + h*4
    const int ar = tid >> 1;
    const int ak = (tid & 1) * 8;

    float acc[2][8][4];
    #pragma unroll
    for (int i = 0; i < 2; i++)
        #pragma unroll
        for (int j = 0; j < 8; j++)
            #pragma unroll
            for (int q = 0; q < 4; q++) acc[i][j][q] = 0.f;

    auto loadA = [&](int k0) {
        int m = bm + ar;
        #pragma unroll
        for (int h = 0; h < 2; h++) {
            int k = k0 + ak + h * 4;
            float4 v = {0.f, 0.f, 0.f, 0.f};
            if (m < M) {
                const float* p = A + (size_t)m * lda + k;
                if (k + 3 < K) v = *(const float4*)p;
                else {
                    if (k + 0 < K) v.x = p[0];
                    if (k + 1 < K) v.y = p[1];
                    if (k + 2 < K) v.z = p[2];
                    if (k + 3 < K) v.w = p[3];
                }
            }
            sa[h][0] = f2tf32(v.x); sa[h][1] = f2tf32(v.y);
            sa[h][2] = f2tf32(v.z); sa[h][3] = f2tf32(v.w);
        }
    };
    auto stageA = [&](int buf) {
        #pragma unroll
        for (int h = 0; h < 2; h++)
            *(uint4*)&As[buf][ar][ak + h * 4] = *(uint4*)sa[h];
    };

    auto loadB = [&](int k0) {
        if (!TB) {
            // B is [K][N]; thread: k = tid>>4, n = (tid&15)*8 + h*4
            int k = k0 + (tid >> 4);
            #pragma unroll
            for (int h = 0; h < 2; h++) {
                int n = bn + (tid & 15) * 8 + h * 4;
                float4 v = {0.f, 0.f, 0.f, 0.f};
                if (k < K) {
                    const float* p = B + (size_t)k * ldb + n;
                    if (n + 3 < N) v = *(const float4*)p;
                    else {
                        if (n + 0 < N) v.x = p[0];
                        if (n + 1 < N) v.y = p[1];
                        if (n + 2 < N) v.z = p[2];
                        if (n + 3 < N) v.w = p[3];
                    }
                }
                sb[h][0] = f2tf32(v.x); sb[h][1] = f2tf32(v.y);
                sb[h][2] = f2tf32(v.z); sb[h][3] = f2tf32(v.w);
            }
        } else {
            // B is [N][K]; thread: n = tid>>1, k = (tid&1)*8 + h*4
            int n = bn + (tid >> 1);
            #pragma unroll
            for (int h = 0; h < 2; h++) {
                int k = k0 + (tid & 1) * 8 + h * 4;
                float4 v = {0.f, 0.f, 0.f, 0.f};
                if (n < N) {
                    const float* p = B + (size_t)n * ldb + k;
                    if (k + 3 < K) v = *(const float4*)p;
                    else {
                        if (k + 0 < K) v.x = p[0];
                        if (k + 1 < K) v.y = p[1];
                        if (k + 2 < K) v.z = p[2];
                        if (k + 3 < K) v.w = p[3];
                    }
                }
                sb[h][0] = f2tf32(v.x); sb[h][1] = f2tf32(v.y);
                sb[h][2] = f2tf32(v.z); sb[h][3] = f2tf32(v.w);
            }
        }
    };
    auto stageB = [&](int buf) {
        if (!TB) {
            int k = tid >> 4;
            #pragma unroll
            for (int h = 0; h < 2; h++)
                *(uint4*)&Bs[buf][k][(tid & 15) * 8 + h * 4] = *(uint4*)sb[h];
        } else {
            int n = tid >> 1;
            #pragma unroll
            for (int h = 0; h < 2; h++) {
                int k = (tid & 1) * 8 + h * 4;
                Bs[buf][k + 0][n] = sb[h][0];
                Bs[buf][k + 1][n] = sb[h][1];
                Bs[buf][k + 2][n] = sb[h][2];
                Bs[buf][k + 3][n] = sb[h][3];
            }
        }
    };

    loadA(0); loadB(0);
    stageA(0); stageB(0);
    __syncthreads();

    const int nk = (K + GBK - 1) / GBK;
    int buf = 0;
    for (int t = 0; t < nk; t++) {
        bool more = (t + 1 < nk);
        if (more) { loadA((t + 1) * GBK); loadB((t + 1) * GBK); }

        #pragma unroll
        for (int ks = 0; ks < 2; ks++) {
            const int kof = ks * 8;
            unsigned af[2][4], bf[8][2];
            #pragma unroll
            for (int i = 0; i < 2; i++) {
                int r = wm * 32 + i * 16;
                af[i][0] = As[buf][r + grp    ][kof + tig    ];
                af[i][1] = As[buf][r + grp + 8][kof + tig    ];
                af[i][2] = As[buf][r + grp    ][kof + tig + 4];
                af[i][3] = As[buf][r + grp + 8][kof + tig + 4];
            }
            #pragma unroll
            for (int j = 0; j < 8; j++) {
                int c = wn * 64 + j * 8 + grp;
                bf[j][0] = Bs[buf][kof + tig    ][c];
                bf[j][1] = Bs[buf][kof + tig + 4][c];
            }
            #pragma unroll
            for (int i = 0; i < 2; i++)
                #pragma unroll
                for (int j = 0; j < 8; j++)
                    mma_tf32(acc[i][j], af[i][0], af[i][1], af[i][2], af[i][3],
                             bf[j][0], bf[j][1]);
        }

        if (more) {
            stageA(buf ^ 1); stageB(buf ^ 1);
            __syncthreads();
            buf ^= 1;
        }
    }

    // epilogue: c0,c1 at (row, 2*tig), (row, 2*tig+1); c2,c3 at row+8
    #pragma unroll
    for (int i = 0; i < 2; i++) {
        int r0 = bm + wm * 32 + i * 16 + grp;
        int r1 = r0 + 8;
        #pragma unroll
        for (int j = 0; j < 8; j++) {
            int c = bn + wn * 64 + j * 8 + 2 * tig;
            if (r0 < M) {
                if (c + 1 < N) *(float2*)&C[(size_t)r0 * ldc + c] = make_float2(acc[i][j][0], acc[i][j][1]);
                else if (c < N) C[(size_t)r0 * ldc + c] = acc[i][j][0];
            }
            if (r1 < M) {
                if (c + 1 < N) *(float2*)&C[(size_t)r1 * ldc + c] = make_float2(acc[i][j][2], acc[i][j][3]);
                else if (c < N) C[(size_t)r1 * ldc + c] = acc[i][j][2];
            }
        }
    }
}

static void sgemm(const float* A, const float* B, float* C,
                  int M, int N, int K, int lda, int ldb, int ldc, bool transB) {
    dim3 grid((N + GBN - 1) / GBN, (M + GBM - 1) / GBM);
    if (transB) tf32_gemm<true ><<<grid, 256>>>(A, B, C, M, N, K, lda, ldb, ldc);
    else        tf32_gemm<false><<<grid, 256>>>(A, B, C, M, N, K, lda, ldb, ldc);
}

// ---------------- GAT attention pieces ----------------

__device__ __forceinline__ unsigned encf(float f) {
    unsigned u = __float_as_uint(f);
    return (u & 0x80000000u) ? ~u : (u | 0x80000000u);
}
__device__ __forceinline__ float decf(unsigned u) {
    return (u & 0x80000000u) ? __uint_as_float(u & 0x7fffffffu) : __uint_as_float(~u);
}

__global__ void node_dots_kernel(const float* __restrict__ H,
                                 const float* __restrict__ a_src,
                                 const float* __restrict__ a_dst,
                                 float* __restrict__ es, float* __restrict__ ed,
                                 int N, int D) {
    int warp = (blockIdx.x * blockDim.x + threadIdx.x) >> 5;
    int lane = threadIdx.x & 31;
    if (warp >= N) return;
    const float* row = H + (size_t)warp * D;
    float s1 = 0.f, s2 = 0.f;
    for (int j = lane; j < D; j += 32) {
        float v = row[j];
        s1 += v * a_src[j];
        s2 += v * a_dst[j];
    }
    #pragma unroll
    for (int o = 16; o; o >>= 1) {
        s1 += __shfl_down_sync(0xffffffffu, s1, o);
        s2 += __shfl_down_sync(0xffffffffu, s2, o);
    }
    if (lane == 0) { es[warp] = s1; ed[warp] = s2; }
}

__global__ void edge_logits_kernel(const int* __restrict__ src, const int* __restrict__ dst,
                                   const float* __restrict__ es, const float* __restrict__ ed,
                                   float* __restrict__ ebuf, unsigned* __restrict__ mx, int E) {
    int e = blockIdx.x * blockDim.x + threadIdx.x;
    if (e >= E) return;
    float v = es[src[e]] + ed[dst[e]];
    v = v > 0.f ? v : 0.2f * v;
    ebuf[e] = v;
    atomicMax(&mx[dst[e]], encf(v));
}

__global__ void edge_exp_kernel(const int* __restrict__ dst,
                                float* __restrict__ ebuf, const unsigned* __restrict__ mx,
                                float* __restrict__ sum, int E) {
    int e = blockIdx.x * blockDim.x + threadIdx.x;
    if (e >= E) return;
    int d = dst[e];
    unsigned u = mx[d];
    float m = (u == 0u) ? 0.f : decf(u);
    float ex = expf(ebuf[e] - m);
    ebuf[e] = ex;
    atomicAdd(&sum[d], ex);
}

__global__ void edge_agg_kernel(const int* __restrict__ src, const int* __restrict__ dst,
                                const float* __restrict__ H, const float* __restrict__ ebuf,
                                const float* __restrict__ sum, float* __restrict__ out,
                                int E, int D, int ldo) {
    int warp = (blockIdx.x * blockDim.x + threadIdx.x) >> 5;
    int lane = threadIdx.x & 31;
    if (warp >= E) return;
    int s = src[warp], d = dst[warp];
    float alpha = ebuf[warp] / (sum[d] + 1e-16f);
    const float4* hrow = (const float4*)(H + (size_t)s * D);
    float4*       orow = (float4*)(out + (size_t)d * ldo);
    int nv = D >> 2;
    for (int j = lane; j < nv; j += 32) {
        float4 v = hrow[j];
        v.x *= alpha; v.y *= alpha; v.z *= alpha; v.w *= alpha;
        atomicAdd(&orow[j], v);
    }
}

__global__ void elu_kernel(float* __restrict__ x, size_t n) {
    size_t i = (size_t)blockIdx.x * blockDim.x + threadIdx.x;
    if (i >= n) return;
    float v = x[i];
    x[i] = v > 0.f ? v : expm1f(v);
}

__global__ void gather_rows4_kernel(const float4* __restrict__ in, const int* __restrict__ perm,
                                    float4* __restrict__ out, int N, int Dv) {
    size_t i = (size_t)blockIdx.x * blockDim.x + threadIdx.x;
    if (i >= (size_t)N * Dv) return;
    int r = (int)(i / Dv);
    int c = (int)(i - (size_t)r * Dv);
    out[i] = in[(size_t)perm[r] * Dv + c];
}

__global__ void summary_kernel(const float* __restrict__ h2, float* __restrict__ out, int N) {
    int c = blockIdx.x;
    __shared__ float sm[256];
    float s = 0.f;
    for (int i = threadIdx.x; i < N; i += blockDim.x)
        s += h2[(size_t)i * OUTD + c];
    sm[threadIdx.x] = s;
    __syncthreads();
    for (int o = 128; o; o >>= 1) {
        if (threadIdx.x < o) sm[threadIdx.x] += sm[threadIdx.x + o];
        __syncthreads();
    }
    if (threadIdx.x == 0) {
        float m = sm[0] / (float)N;
        out[c] = 1.f / (1.f + expf(-m));
    }
}

// ---------------- host orchestration ----------------

static void run_gat(const float* H, int D,
                    const float* a_src, const float* a_dst,
                    const int* src, const int* dst,
                    float* es, float* ed, unsigned* mx, float* sum, float* ebuf,
                    float* out, int ldo) {
    cudaMemsetAsync(mx, 0, NN * sizeof(unsigned));
    cudaMemsetAsync(sum, 0, NN * sizeof(float));
    node_dots_kernel<<<(NN * 32 + 255) / 256, 256>>>(H, a_src, a_dst, es, ed, NN, D);
    edge_logits_kernel<<<(EE + 255) / 256, 256>>>(src, dst, es, ed, ebuf, mx, EE);
    edge_exp_kernel<<<(EE + 255) / 256, 256>>>(dst, ebuf, mx, sum, EE);
    edge_agg_kernel<<<(EE * 32 + 255) / 256, 256>>>(src, dst, H, ebuf, sum, out, EE, D, ldo);
}

extern "C" void kernel_launch(void* const* d_in, const int* in_sizes, int n_in,
                              void* d_out, int out_size) {
    const float* features    = (const float*)d_in[0];
    const float* im_features = (const float*)d_in[1];
    const float* W1x         = (const float*)d_in[2];
    const float* a1x_src     = (const float*)d_in[3];
    const float* a1x_dst     = (const float*)d_in[4];
    const float* W1r         = (const float*)d_in[5];
    const float* a1r_src     = (const float*)d_in[6];
    const float* a1r_dst     = (const float*)d_in[7];
    const float* W2          = (const float*)d_in[8];
    const float* a3_src      = (const float*)d_in[9];
    const float* a3_dst      = (const float*)d_in[10];
    const int*   edge_index  = (const int*)d_in[11];
    const int*   perm        = (const int*)d_in[12];

    const int* src = edge_index;
    const int* dst = edge_index + EE;

    void* p;
    cudaGetSymbolAddress(&p, g_H1x);  float* H1x  = (float*)p;
    cudaGetSymbolAddress(&p, g_H1r);  float* H1r  = (float*)p;
    cudaGetSymbolAddress(&p, g_Hgx);  float* Hgx  = (float*)p;
    cudaGetSymbolAddress(&p, g_Hgr);  float* Hgr  = (float*)p;
    cudaGetSymbolAddress(&p, g_t);    float* tbuf = (float*)p;
    cudaGetSymbolAddress(&p, g_hdec); float* hdec = (float*)p;
    cudaGetSymbolAddress(&p, g_h3);   float* h3   = (float*)p;
    cudaGetSymbolAddress(&p, g_es);   float* es   = (float*)p;
    cudaGetSymbolAddress(&p, g_ed);   float* ed   = (float*)p;
    cudaGetSymbolAddress(&p, g_mx);   unsigned* mx = (unsigned*)p;
    cudaGetSymbolAddress(&p, g_sum);  float* sumb = (float*)p;
    cudaGetSymbolAddress(&p, g_e);    float* ebuf = (float*)p;

    float* out = (float*)d_out;
    const size_t S_h2  = (size_t)NN * OUTD;
    const size_t S_h4x = (size_t)NN * INX;
    const size_t S_h4r = (size_t)NN * INR;
    const size_t passSz = S_h2 + S_h4x + S_h4r;

    // Big input GEMMs once; permuted pass reuses rows via gather.
    sgemm(features,    W1x, H1x, NN, NH, INX, INX, NH, NH, false);
    sgemm(im_features, W1r, H1r, NN, NH, INR, INR, NH, NH, false);

    for (int pass = 0; pass < 2; pass++) {
        const float* Hx = H1x;
        const float* Hr = H1r;
        if (pass) {
            size_t n4 = (size_t)NN * (NH / 4);
            gather_rows4_kernel<<<(unsigned)((n4 + 255) / 256), 256>>>((const float4*)H1x, perm, (float4*)Hgx, NN, NH / 4);
            gather_rows4_kernel<<<(unsigned)((n4 + 255) / 256), 256>>>((const float4*)H1r, perm, (float4*)Hgr, NN, NH / 4);
            Hx = Hgx; Hr = Hgr;
        }

        cudaMemsetAsync(tbuf, 0, (size_t)NN * D2 * sizeof(float));
        run_gat(Hx, NH, a1x_src, a1x_dst, src, dst, es, ed, mx, sumb, ebuf, tbuf,      D2);
        run_gat(Hr, NH, a1r_src, a1r_dst, src, dst, es, ed, mx, sumb, ebuf, tbuf + NH, D2);
        {
            size_t n = (size_t)NN * D2;
            elu_kernel<<<(unsigned)((n + 255) / 256), 256>>>(tbuf, n);
        }

        float* h2  = out + (size_t)pass * passSz;
        float* h4x = h2 + S_h2;
        float* h4r = h4x + S_h4x;

        sgemm(tbuf, W2, h2, NN, OUTD, D2, D2, OUTD, OUTD, false);
        sgemm(h2, W2, hdec, NN, D2, OUTD, OUTD, OUTD, D2, true);

        cudaMemsetAsync(h3, 0, (size_t)NN * D2 * sizeof(float));
        run_gat(hdec, D2, a3_src, a3_dst, src, dst, es, ed, mx, sumb, ebuf, h3, D2);
        {
            size_t n = (size_t)NN * D2;
            elu_kernel<<<(unsigned)((n + 255) / 256), 256>>>(h3, n);
        }

        sgemm(h3,      W1x, h4x, NN, INX, NH, D2, NH, INX, true);
        sgemm(h3 + NH, W1r, h4r, NN, INR, NH, D2, NH, INR, true);
    }

    summary_kernel<<<OUTD, 256>>>(out, out + 2 * passSz, NN);
}

// round 4
// speedup vs baseline: 3.0947x; 1.1662x over previous
#include <cuda_runtime.h>
#include <cuda_bf16.h>
#include <cstdint>
#include <cstdio>
#include <math_constants.h>

// Problem shape (fixed by the dataset)
#define NN   30000
#define EE   480000
#define INX  3000
#define INR  2048
#define NH   256
#define OUTD 64
#define D2   (2*NH)   // 512

// ---------------- scratch (device globals; no allocs allowed) ----------------
__device__ float    g_H1x [(size_t)NN*NH];
__device__ float    g_H1r [(size_t)NN*NH];
__device__ float    g_Hgx [(size_t)NN*NH];
__device__ float    g_Hgr [(size_t)NN*NH];
__device__ float    g_t   [(size_t)NN*D2];
__device__ float    g_hdec[(size_t)NN*D2];
__device__ float    g_h3  [(size_t)NN*D2];
__device__ float    g_es  [NN];
__device__ float    g_ed  [NN];
__device__ int      g_deg [NN];
__device__ int      g_rs  [NN + 1];
__device__ int      g_cur [NN];
__device__ int      g_csrc[EE];

// ---------------- TF32 tensor-core GEMM ----------------
#define GBM 128
#define GBN 128
#define GBK 16
#define AS_STRIDE 20
#define BS_STRIDE 132

__device__ __forceinline__ unsigned f2tf32(float f) {
    unsigned r;
    asm("cvt.rna.tf32.f32 %0, %1;" : "=r"(r) : "f"(f));
    return r;
}

__device__ __forceinline__ void mma_tf32(float c[4],
                                         unsigned a0, unsigned a1, unsigned a2, unsigned a3,
                                         unsigned b0, unsigned b1) {
    asm volatile(
        "mma.sync.aligned.m16n8k8.row.col.f32.tf32.tf32.f32 "
        "{%0,%1,%2,%3}, {%4,%5,%6,%7}, {%8,%9}, {%0,%1,%2,%3};"
        : "+f"(c[0]), "+f"(c[1]), "+f"(c[2]), "+f"(c[3])
        : "r"(a0), "r"(a1), "r"(a2), "r"(a3), "r"(b0), "r"(b1));
}

template<bool TB>
__global__ __launch_bounds__(256)
void tf32_gemm(const float* __restrict__ A, const float* __restrict__ B,
               float* __restrict__ C, int M, int N, int K,
               int lda, int ldb, int ldc) {
    __shared__ unsigned As[2][GBM][AS_STRIDE];
    __shared__ unsigned Bs[2][GBK][BS_STRIDE];

    const int tid  = threadIdx.x;
    const int lane = tid & 31;
    const int wid  = tid >> 5;
    const int wm   = wid & 3;
    const int wn   = wid >> 2;
    const int bm   = blockIdx.y * GBM;
    const int bn   = blockIdx.x * GBN;
    const int grp  = lane >> 2;
    const int tig  = lane & 3;

    unsigned sa[2][4];
    unsigned sb[2][4];
    const int ar = tid >> 1;
    const int ak = (tid & 1) * 8;

    float acc[2][8][4];
    #pragma unroll
    for (int i = 0; i < 2; i++)
        #pragma unroll
        for (int j = 0; j < 8; j++)
            #pragma unroll
            for (int q = 0; q < 4; q++) acc[i][j][q] = 0.f;

    auto loadA = [&](int k0) {
        int m = bm + ar;
        #pragma unroll
        for (int h = 0; h < 2; h++) {
            int k = k0 + ak + h * 4;
            float4 v = {0.f, 0.f, 0.f, 0.f};
            if (m < M) {
                const float* p = A + (size_t)m * lda + k;
                if (k + 3 < K) v = *(const float4*)p;
                else {
                    if (k + 0 < K) v.x = p[0];
                    if (k + 1 < K) v.y = p[1];
                    if (k + 2 < K) v.z = p[2];
                    if (k + 3 < K) v.w = p[3];
                }
            }
            sa[h][0] = f2tf32(v.x); sa[h][1] = f2tf32(v.y);
            sa[h][2] = f2tf32(v.z); sa[h][3] = f2tf32(v.w);
        }
    };
    auto stageA = [&](int buf) {
        #pragma unroll
        for (int h = 0; h < 2; h++)
            *(uint4*)&As[buf][ar][ak + h * 4] = *(uint4*)sa[h];
    };

    auto loadB = [&](int k0) {
        if (!TB) {
            int k = k0 + (tid >> 4);
            #pragma unroll
            for (int h = 0; h < 2; h++) {
                int n = bn + (tid & 15) * 8 + h * 4;
                float4 v = {0.f, 0.f, 0.f, 0.f};
                if (k < K) {
                    const float* p = B + (size_t)k * ldb + n;
                    if (n + 3 < N) v = *(const float4*)p;
                    else {
                        if (n + 0 < N) v.x = p[0];
                        if (n + 1 < N) v.y = p[1];
                        if (n + 2 < N) v.z = p[2];
                        if (n + 3 < N) v.w = p[3];
                    }
                }
                sb[h][0] = f2tf32(v.x); sb[h][1] = f2tf32(v.y);
                sb[h][2] = f2tf32(v.z); sb[h][3] = f2tf32(v.w);
            }
        } else {
            int n = bn + (tid >> 1);
            #pragma unroll
            for (int h = 0; h < 2; h++) {
                int k = k0 + (tid & 1) * 8 + h * 4;
                float4 v = {0.f, 0.f, 0.f, 0.f};
                if (n < N) {
                    const float* p = B + (size_t)n * ldb + k;
                    if (k + 3 < K) v = *(const float4*)p;
                    else {
                        if (k + 0 < K) v.x = p[0];
                        if (k + 1 < K) v.y = p[1];
                        if (k + 2 < K) v.z = p[2];
                        if (k + 3 < K) v.w = p[3];
                    }
                }
                sb[h][0] = f2tf32(v.x); sb[h][1] = f2tf32(v.y);
                sb[h][2] = f2tf32(v.z); sb[h][3] = f2tf32(v.w);
            }
        }
    };
    auto stageB = [&](int buf) {
        if (!TB) {
            int k = tid >> 4;
            #pragma unroll
            for (int h = 0; h < 2; h++)
                *(uint4*)&Bs[buf][k][(tid & 15) * 8 + h * 4] = *(uint4*)sb[h];
        } else {
            int n = tid >> 1;
            #pragma unroll
            for (int h = 0; h < 2; h++) {
                int k = (tid & 1) * 8 + h * 4;
                Bs[buf][k + 0][n] = sb[h][0];
                Bs[buf][k + 1][n] = sb[h][1];
                Bs[buf][k + 2][n] = sb[h][2];
                Bs[buf][k + 3][n] = sb[h][3];
            }
        }
    };

    loadA(0); loadB(0);
    stageA(0); stageB(0);
    __syncthreads();

    const int nk = (K + GBK - 1) / GBK;
    int buf = 0;
    for (int t = 0; t < nk; t++) {
        bool more = (t + 1 < nk);
        if (more) { loadA((t + 1) * GBK); loadB((t + 1) * GBK); }

        #pragma unroll
        for (int ks = 0; ks < 2; ks++) {
            const int kof = ks * 8;
            unsigned af[2][4], bf[8][2];
            #pragma unroll
            for (int i = 0; i < 2; i++) {
                int r = wm * 32 + i * 16;
                af[i][0] = As[buf][r + grp    ][kof + tig    ];
                af[i][1] = As[buf][r + grp + 8][kof + tig    ];
                af[i][2] = As[buf][r + grp    ][kof + tig + 4];
                af[i][3] = As[buf][r + grp + 8][kof + tig + 4];
            }
            #pragma unroll
            for (int j = 0; j < 8; j++) {
                int c = wn * 64 + j * 8 + grp;
                bf[j][0] = Bs[buf][kof + tig    ][c];
                bf[j][1] = Bs[buf][kof + tig + 4][c];
            }
            #pragma unroll
            for (int i = 0; i < 2; i++)
                #pragma unroll
                for (int j = 0; j < 8; j++)
                    mma_tf32(acc[i][j], af[i][0], af[i][1], af[i][2], af[i][3],
                             bf[j][0], bf[j][1]);
        }

        if (more) {
            stageA(buf ^ 1); stageB(buf ^ 1);
            __syncthreads();
            buf ^= 1;
        }
    }

    #pragma unroll
    for (int i = 0; i < 2; i++) {
        int r0 = bm + wm * 32 + i * 16 + grp;
        int r1 = r0 + 8;
        #pragma unroll
        for (int j = 0; j < 8; j++) {
            int c = bn + wn * 64 + j * 8 + 2 * tig;
            if (r0 < M) {
                if (c + 1 < N) *(float2*)&C[(size_t)r0 * ldc + c] = make_float2(acc[i][j][0], acc[i][j][1]);
                else if (c < N) C[(size_t)r0 * ldc + c] = acc[i][j][0];
            }
            if (r1 < M) {
                if (c + 1 < N) *(float2*)&C[(size_t)r1 * ldc + c] = make_float2(acc[i][j][2], acc[i][j][3]);
                else if (c < N) C[(size_t)r1 * ldc + c] = acc[i][j][2];
            }
        }
    }
}

static void sgemm(const float* A, const float* B, float* C,
                  int M, int N, int K, int lda, int ldb, int ldc, bool transB) {
    dim3 grid((N + GBN - 1) / GBN, (M + GBM - 1) / GBM);
    if (transB) tf32_gemm<true ><<<grid, 256>>>(A, B, C, M, N, K, lda, ldb, ldc);
    else        tf32_gemm<false><<<grid, 256>>>(A, B, C, M, N, K, lda, ldb, ldc);
}

// ---------------- CSR build (per launch; graph static across all 6 GATs) ----------------

__global__ void deg_kernel(const int* __restrict__ dst, int* __restrict__ deg, int E) {
    int e = blockIdx.x * blockDim.x + threadIdx.x;
    if (e < E) atomicAdd(&deg[dst[e]], 1);
}

// single-block exclusive scan over N elements -> rs[0..N]
__global__ void scan_kernel(const int* __restrict__ deg, int* __restrict__ rs, int N) {
    __shared__ int sm[1024];
    __shared__ int carry_s;
    if (threadIdx.x == 0) carry_s = 0;
    __syncthreads();
    for (int base = 0; base < N; base += 1024) {
        int i = base + threadIdx.x;
        int v = (i < N) ? deg[i] : 0;
        sm[threadIdx.x] = v;
        __syncthreads();
        #pragma unroll
        for (int off = 1; off < 1024; off <<= 1) {
            int t = (threadIdx.x >= off) ? sm[threadIdx.x - off] : 0;
            __syncthreads();
            sm[threadIdx.x] += t;
            __syncthreads();
        }
        int incl = sm[threadIdx.x];
        int carry = carry_s;
        if (i < N) rs[i] = carry + incl - v;
        int total = sm[1023];
        __syncthreads();
        if (threadIdx.x == 0) carry_s = carry + total;
        __syncthreads();
    }
    if (threadIdx.x == 0) rs[N] = carry_s;
}

__global__ void scatter_kernel(const int* __restrict__ src, const int* __restrict__ dst,
                               int* __restrict__ cur, int* __restrict__ csrc, int E) {
    int e = blockIdx.x * blockDim.x + threadIdx.x;
    if (e >= E) return;
    int slot = atomicAdd(&cur[dst[e]], 1);
    csrc[slot] = src[e];
}

// ---------------- fused GAT: softmax + aggregate + ELU, warp per node ----------------
// out[node, 0:D) (stride ldo) = elu( sum_e alpha_e * H[src_e, :] )
template<int DCH>   // DCH = D/128 float4 chunks per lane
__global__ void gat_fused_kernel(const float* __restrict__ H,
                                 const float* __restrict__ es,
                                 const float* __restrict__ ed,
                                 const int* __restrict__ rs,
                                 const int* __restrict__ csrc,
                                 float* __restrict__ out, int ldo, int N) {
    int node = (blockIdx.x * blockDim.x + threadIdx.x) >> 5;
    int lane = threadIdx.x & 31;
    if (node >= N) return;
    int s0 = rs[node], s1 = rs[node + 1];

    float4 acc[DCH];
    #pragma unroll
    for (int c = 0; c < DCH; c++) acc[c] = make_float4(0.f, 0.f, 0.f, 0.f);

    if (s0 < s1) {
        const float edv = ed[node];
        float mx = -CUDART_INF_F;
        for (int i = s0 + lane; i < s1; i += 32) {
            float v = es[csrc[i]] + edv;
            v = v > 0.f ? v : 0.2f * v;
            mx = fmaxf(mx, v);
        }
        #pragma unroll
        for (int o = 16; o; o >>= 1) mx = fmaxf(mx, __shfl_xor_sync(0xffffffffu, mx, o));

        float ssum = 0.f;
        for (int i = s0 + lane; i < s1; i += 32) {
            float v = es[csrc[i]] + edv;
            v = v > 0.f ? v : 0.2f * v;
            ssum += expf(v - mx);
        }
        #pragma unroll
        for (int o = 16; o; o >>= 1) ssum += __shfl_xor_sync(0xffffffffu, ssum, o);
        float inv = 1.f / (ssum + 1e-16f);

        for (int i = s0; i < s1; i++) {
            int s = csrc[i];                       // broadcast load
            float v = es[s] + edv;
            v = v > 0.f ? v : 0.2f * v;
            float alpha = expf(v - mx) * inv;
            const float4* hrow = (const float4*)(H + (size_t)s * (DCH * 128));
            #pragma unroll
            for (int c = 0; c < DCH; c++) {
                float4 hv = hrow[c * 32 + lane];
                acc[c].x = fmaf(alpha, hv.x, acc[c].x);
                acc[c].y = fmaf(alpha, hv.y, acc[c].y);
                acc[c].z = fmaf(alpha, hv.z, acc[c].z);
                acc[c].w = fmaf(alpha, hv.w, acc[c].w);
            }
        }
    }

    float4* orow = (float4*)(out + (size_t)node * ldo);
    #pragma unroll
    for (int c = 0; c < DCH; c++) {
        float4 v = acc[c];
        v.x = v.x > 0.f ? v.x : expm1f(v.x);
        v.y = v.y > 0.f ? v.y : expm1f(v.y);
        v.z = v.z > 0.f ? v.z : expm1f(v.z);
        v.w = v.w > 0.f ? v.w : expm1f(v.w);
        orow[c * 32 + lane] = v;
    }
}

// ---------------- misc kernels ----------------

__global__ void node_dots_kernel(const float* __restrict__ H,
                                 const float* __restrict__ a_src,
                                 const float* __restrict__ a_dst,
                                 float* __restrict__ es, float* __restrict__ ed,
                                 int N, int D) {
    int warp = (blockIdx.x * blockDim.x + threadIdx.x) >> 5;
    int lane = threadIdx.x & 31;
    if (warp >= N) return;
    const float* row = H + (size_t)warp * D;
    float s1 = 0.f, s2 = 0.f;
    for (int j = lane; j < D; j += 32) {
        float v = row[j];
        s1 += v * a_src[j];
        s2 += v * a_dst[j];
    }
    #pragma unroll
    for (int o = 16; o; o >>= 1) {
        s1 += __shfl_down_sync(0xffffffffu, s1, o);
        s2 += __shfl_down_sync(0xffffffffu, s2, o);
    }
    if (lane == 0) { es[warp] = s1; ed[warp] = s2; }
}

__global__ void gather_rows4_kernel(const float4* __restrict__ in, const int* __restrict__ perm,
                                    float4* __restrict__ out, int N, int Dv) {
    size_t i = (size_t)blockIdx.x * blockDim.x + threadIdx.x;
    if (i >= (size_t)N * Dv) return;
    int r = (int)(i / Dv);
    int c = (int)(i - (size_t)r * Dv);
    out[i] = in[(size_t)perm[r] * Dv + c];
}

__global__ void summary_kernel(const float* __restrict__ h2, float* __restrict__ out, int N) {
    int c = blockIdx.x;
    __shared__ float sm[256];
    float s = 0.f;
    for (int i = threadIdx.x; i < N; i += blockDim.x)
        s += h2[(size_t)i * OUTD + c];
    sm[threadIdx.x] = s;
    __syncthreads();
    for (int o = 128; o; o >>= 1) {
        if (threadIdx.x < o) sm[threadIdx.x] += sm[threadIdx.x + o];
        __syncthreads();
    }
    if (threadIdx.x == 0) {
        float m = sm[0] / (float)N;
        out[c] = 1.f / (1.f + expf(-m));
    }
}

// ---------------- host orchestration ----------------

template<int DCH>
static void run_gat(const float* H,
                    const float* a_src, const float* a_dst,
                    const int* rs, const int* csrc,
                    float* es, float* ed,
                    float* out, int ldo) {
    node_dots_kernel<<<(NN * 32 + 255) / 256, 256>>>(H, a_src, a_dst, es, ed, NN, DCH * 128);
    gat_fused_kernel<DCH><<<(NN * 8 * 32 + 255) / 256, 256>>>(H, es, ed, rs, csrc, out, ldo, NN);
}

extern "C" void kernel_launch(void* const* d_in, const int* in_sizes, int n_in,
                              void* d_out, int out_size) {
    const float* features    = (const float*)d_in[0];
    const float* im_features = (const float*)d_in[1];
    const float* W1x         = (const float*)d_in[2];
    const float* a1x_src     = (const float*)d_in[3];
    const float* a1x_dst     = (const float*)d_in[4];
    const float* W1r         = (const float*)d_in[5];
    const float* a1r_src     = (const float*)d_in[6];
    const float* a1r_dst     = (const float*)d_in[7];
    const float* W2          = (const float*)d_in[8];
    const float* a3_src      = (const float*)d_in[9];
    const float* a3_dst      = (const float*)d_in[10];
    const int*   edge_index  = (const int*)d_in[11];
    const int*   perm        = (const int*)d_in[12];

    const int* src = edge_index;
    const int* dst = edge_index + EE;

    void* p;
    cudaGetSymbolAddress(&p, g_H1x);  float* H1x  = (float*)p;
    cudaGetSymbolAddress(&p, g_H1r);  float* H1r  = (float*)p;
    cudaGetSymbolAddress(&p, g_Hgx);  float* Hgx  = (float*)p;
    cudaGetSymbolAddress(&p, g_Hgr);  float* Hgr  = (float*)p;
    cudaGetSymbolAddress(&p, g_t);    float* tbuf = (float*)p;
    cudaGetSymbolAddress(&p, g_hdec); float* hdec = (float*)p;
    cudaGetSymbolAddress(&p, g_h3);   float* h3   = (float*)p;
    cudaGetSymbolAddress(&p, g_es);   float* es   = (float*)p;
    cudaGetSymbolAddress(&p, g_ed);   float* ed   = (float*)p;
    cudaGetSymbolAddress(&p, g_deg);  int*   deg  = (int*)p;
    cudaGetSymbolAddress(&p, g_rs);   int*   rs   = (int*)p;
    cudaGetSymbolAddress(&p, g_cur);  int*   cur  = (int*)p;
    cudaGetSymbolAddress(&p, g_csrc); int*   csrc = (int*)p;

    float* out = (float*)d_out;
    const size_t S_h2  = (size_t)NN * OUTD;
    const size_t S_h4x = (size_t)NN * INX;
    const size_t S_h4r = (size_t)NN * INR;
    const size_t passSz = S_h2 + S_h4x + S_h4r;

    // ---- CSR build (once per launch; shared by all 6 GATs) ----
    cudaMemsetAsync(deg, 0, NN * sizeof(int));
    deg_kernel<<<(EE + 255) / 256, 256>>>(dst, deg, EE);
    scan_kernel<<<1, 1024>>>(deg, rs, NN);
    cudaMemcpyAsync(cur, rs, NN * sizeof(int), cudaMemcpyDeviceToDevice);
    scatter_kernel<<<(EE + 255) / 256, 256>>>(src, dst, cur, csrc, EE);

    // Big input GEMMs once; permuted pass reuses rows via gather.
    sgemm(features,    W1x, H1x, NN, NH, INX, INX, NH, NH, false);
    sgemm(im_features, W1r, H1r, NN, NH, INR, INR, NH, NH, false);

    for (int pass = 0; pass < 2; pass++) {
        const float* Hx = H1x;
        const float* Hr = H1r;
        if (pass) {
            size_t n4 = (size_t)NN * (NH / 4);
            gather_rows4_kernel<<<(unsigned)((n4 + 255) / 256), 256>>>((const float4*)H1x, perm, (float4*)Hgx, NN, NH / 4);
            gather_rows4_kernel<<<(unsigned)((n4 + 255) / 256), 256>>>((const float4*)H1r, perm, (float4*)Hgr, NN, NH / 4);
            Hx = Hgx; Hr = Hgr;
        }

        // encode: two fused GATs (ELU folded in) into halves of tbuf
        run_gat<2>(Hx, a1x_src, a1x_dst, rs, csrc, es, ed, tbuf,      D2);
        run_gat<2>(Hr, a1r_src, a1r_dst, rs, csrc, es, ed, tbuf + NH, D2);

        float* h2  = out + (size_t)pass * passSz;
        float* h4x = h2 + S_h2;
        float* h4r = h4x + S_h4x;

        sgemm(tbuf, W2, h2, NN, OUTD, D2, D2, OUTD, OUTD, false);
        sgemm(h2, W2, hdec, NN, D2, OUTD, OUTD, OUTD, D2, true);

        // decode fused GAT (ELU folded in)
        run_gat<4>(hdec, a3_src, a3_dst, rs, csrc, es, ed, h3, D2);

        sgemm(h3,      W1x, h4x, NN, INX, NH, D2, NH, INX, true);
        sgemm(h3 + NH, W1r, h4r, NN, INR, NH, D2, NH, INR, true);
    }

    summary_kernel<<<OUTD, 256>>>(out, out + 2 * passSz, NN);
}

// round 6
// speedup vs baseline: 4.0503x; 1.3088x over previous
#include <cuda_runtime.h>
#include <cuda_bf16.h>
#include <cstdint>
#include <cstdio>
#include <math_constants.h>

// Problem shape (fixed by the dataset)
#define NN   30000
#define EE   480000
#define INX  3000
#define INR  2048
#define NH   256
#define OUTD 64
#define D2   (2*NH)   // 512

// ---------------- scratch (device globals; no allocs allowed) ----------------
__device__ float    g_H1x [(size_t)NN*NH];
__device__ float    g_H1r [(size_t)NN*NH];
__device__ float    g_Hgx [(size_t)NN*NH];
__device__ float    g_Hgr [(size_t)NN*NH];
__device__ float    g_t   [(size_t)NN*D2];
__device__ float    g_hdec[(size_t)NN*D2];
__device__ float    g_h3  [(size_t)NN*D2];
__device__ float    g_es  [NN];
__device__ float    g_ed  [NN];
__device__ int      g_deg [NN];
__device__ int      g_rs  [NN + 1];
__device__ int      g_cur [NN];
__device__ int      g_csrc[EE];

// ---------------- TF32 tensor-core GEMM, cp.async 4-stage pipeline ----------------
// C[M,N] = A[M,K] @ B      (TB=false, B is K x N)
// C[M,N] = A[M,K] @ B^T    (TB=true,  B is N x K)
#define GBM 128
#define GBN 128
#define GBK 16
#define STAGES 4
#define AS_STRIDE 20           // 16 + 4 pad, conflict-free fragment LDS
#define BS_STRIDE_KN 136       // !TB: [k][n] rows, 128+8 pad (8%32 pattern disjoint)
#define BS_STRIDE_NK 20        // TB:  [n][k] rows, like A

#define A_STG (GBM * AS_STRIDE)                 // floats per A stage

__device__ __forceinline__ unsigned f2tf32(float f) {
    unsigned r;
    asm("cvt.rna.tf32.f32 %0, %1;" : "=r"(r) : "f"(f));
    return r;
}

__device__ __forceinline__ void cp_async16(uint32_t saddr, const void* gptr, int src_size) {
    asm volatile("cp.async.cg.shared.global [%0], [%1], 16, %2;\n"
                 :: "r"(saddr), "l"(gptr), "r"(src_size));
}
__device__ __forceinline__ void cp_commit() {
    asm volatile("cp.async.commit_group;\n");
}
template<int NWAIT>
__device__ __forceinline__ void cp_wait() {
    asm volatile("cp.async.wait_group %0;\n" :: "n"(NWAIT));
}

__device__ __forceinline__ void mma_tf32(float c[4],
                                         unsigned a0, unsigned a1, unsigned a2, unsigned a3,
                                         unsigned b0, unsigned b1) {
    asm volatile(
        "mma.sync.aligned.m16n8k8.row.col.f32.tf32.tf32.f32 "
        "{%0,%1,%2,%3}, {%4,%5,%6,%7}, {%8,%9}, {%0,%1,%2,%3};"
        : "+f"(c[0]), "+f"(c[1]), "+f"(c[2]), "+f"(c[3])
        : "r"(a0), "r"(a1), "r"(a2), "r"(a3), "r"(b0), "r"(b1));
}

template<bool TB>
__global__ __launch_bounds__(256)
void tf32_gemm(const float* __restrict__ A, const float* __restrict__ B,
               float* __restrict__ C, int M, int N, int K,
               int lda, int ldb, int ldc) {
    constexpr int B_STG = TB ? (GBN * BS_STRIDE_NK) : (GBK * BS_STRIDE_KN);

    extern __shared__ float smem[];
    float* As = smem;                       // STAGES * A_STG
    float* Bs = smem + STAGES * A_STG;      // STAGES * B_STG

    const int tid  = threadIdx.x;
    const int lane = tid & 31;
    const int wid  = tid >> 5;
    const int wm   = wid & 3;
    const int wn   = wid >> 2;
    const int bm   = blockIdx.y * GBM;
    const int bn   = blockIdx.x * GBN;
    const int grp  = lane >> 2;
    const int tig  = lane & 3;

    float acc[2][8][4];
    #pragma unroll
    for (int i = 0; i < 2; i++)
        #pragma unroll
        for (int j = 0; j < 8; j++)
            #pragma unroll
            for (int q = 0; q < 4; q++) acc[i][j][q] = 0.f;

    // ---- async tile issue ----
    const int ar  = tid >> 1;               // A row 0..127 (also TB B row)
    const int ah  = (tid & 1) * 2;          // float4 index base {0,2}

    auto issue_tile = [&](int t, int stage) {
        const int k0 = t * GBK;
        // A tile: [128][16]
        {
            int m = bm + ar;
            const float* gbase = A + (size_t)min(m, M - 1) * lda;
            #pragma unroll
            for (int h = 0; h < 2; h++) {
                int q = ah + h;             // 0..3
                int k = k0 + q * 4;
                bool ok = (m < M) && (k + 4 <= K);
                uint32_t sa = (uint32_t)__cvta_generic_to_shared(
                    &As[stage * A_STG + ar * AS_STRIDE + q * 4]);
                cp_async16(sa, gbase + (ok ? k : 0), ok ? 16 : 0);
            }
        }
        if (!TB) {
            // B tile: [16][128], row k, col n
            int kr = tid >> 4;              // 0..15
            int nqb = (tid & 15) * 2;       // float4 col base
            const float* gbase = B + (size_t)min(k0 + kr, K - 1) * ldb;
            #pragma unroll
            for (int h = 0; h < 2; h++) {
                int q = nqb + h;            // 0..31
                int n = bn + q * 4;
                bool ok = (k0 + kr < K) && (n + 4 <= N);
                uint32_t sa = (uint32_t)__cvta_generic_to_shared(
                    &Bs[stage * B_STG + kr * BS_STRIDE_KN + q * 4]);
                cp_async16(sa, gbase + (ok ? n : 0), ok ? 16 : 0);
            }
        } else {
            // B tile: [128][16], row n, col k
            int n = bn + ar;
            const float* gbase = B + (size_t)min(n, N - 1) * ldb;
            #pragma unroll
            for (int h = 0; h < 2; h++) {
                int q = ah + h;
                int k = k0 + q * 4;
                bool ok = (n < N) && (k + 4 <= K);
                uint32_t sa = (uint32_t)__cvta_generic_to_shared(
                    &Bs[stage * B_STG + ar * BS_STRIDE_NK + q * 4]);
                cp_async16(sa, gbase + (ok ? k : 0), ok ? 16 : 0);
            }
        }
    };

    const int nk = (K + GBK - 1) / GBK;

    #pragma unroll
    for (int s = 0; s < STAGES - 1; s++) {
        if (s < nk) issue_tile(s, s);
        cp_commit();
    }

    for (int t = 0; t < nk; t++) {
        cp_wait<STAGES - 2>();
        __syncthreads();
        const int buf = t % STAGES;
        const float* Ab = &As[buf * A_STG];
        const float* Bb = &Bs[buf * B_STG];

        #pragma unroll
        for (int ks = 0; ks < 2; ks++) {
            const int kof = ks * 8;
            unsigned af[2][4], bf[8][2];
            #pragma unroll
            for (int i = 0; i < 2; i++) {
                int r = wm * 32 + i * 16;
                af[i][0] = f2tf32(Ab[(r + grp    ) * AS_STRIDE + kof + tig    ]);
                af[i][1] = f2tf32(Ab[(r + grp + 8) * AS_STRIDE + kof + tig    ]);
                af[i][2] = f2tf32(Ab[(r + grp    ) * AS_STRIDE + kof + tig + 4]);
                af[i][3] = f2tf32(Ab[(r + grp + 8) * AS_STRIDE + kof + tig + 4]);
            }
            #pragma unroll
            for (int j = 0; j < 8; j++) {
                int c = wn * 64 + j * 8 + grp;
                if (!TB) {
                    bf[j][0] = f2tf32(Bb[(kof + tig    ) * BS_STRIDE_KN + c]);
                    bf[j][1] = f2tf32(Bb[(kof + tig + 4) * BS_STRIDE_KN + c]);
                } else {
                    bf[j][0] = f2tf32(Bb[c * BS_STRIDE_NK + kof + tig    ]);
                    bf[j][1] = f2tf32(Bb[c * BS_STRIDE_NK + kof + tig + 4]);
                }
            }
            #pragma unroll
            for (int i = 0; i < 2; i++)
                #pragma unroll
                for (int j = 0; j < 8; j++)
                    mma_tf32(acc[i][j], af[i][0], af[i][1], af[i][2], af[i][3],
                             bf[j][0], bf[j][1]);
        }

        int nt = t + STAGES - 1;
        if (nt < nk) issue_tile(nt, nt % STAGES);
        cp_commit();
    }

    #pragma unroll
    for (int i = 0; i < 2; i++) {
        int r0 = bm + wm * 32 + i * 16 + grp;
        int r1 = r0 + 8;
        #pragma unroll
        for (int j = 0; j < 8; j++) {
            int c = bn + wn * 64 + j * 8 + 2 * tig;
            if (r0 < M) {
                if (c + 1 < N) *(float2*)&C[(size_t)r0 * ldc + c] = make_float2(acc[i][j][0], acc[i][j][1]);
                else if (c < N) C[(size_t)r0 * ldc + c] = acc[i][j][0];
            }
            if (r1 < M) {
                if (c + 1 < N) *(float2*)&C[(size_t)r1 * ldc + c] = make_float2(acc[i][j][2], acc[i][j][3]);
                else if (c < N) C[(size_t)r1 * ldc + c] = acc[i][j][2];
            }
        }
    }
}

static int smem_bytes(bool transB) {
    int bstg = transB ? (GBN * BS_STRIDE_NK) : (GBK * BS_STRIDE_KN);
    return (STAGES * A_STG + STAGES * bstg) * 4;
}

static void sgemm(const float* A, const float* B, float* C,
                  int M, int N, int K, int lda, int ldb, int ldc, bool transB) {
    dim3 grid((N + GBN - 1) / GBN, (M + GBM - 1) / GBM);
    if (transB) tf32_gemm<true ><<<grid, 256, smem_bytes(true )>>>(A, B, C, M, N, K, lda, ldb, ldc);
    else        tf32_gemm<false><<<grid, 256, smem_bytes(false)>>>(A, B, C, M, N, K, lda, ldb, ldc);
}

// ---------------- CSR build (per launch; graph static across all 6 GATs) ----------------

__global__ void deg_kernel(const int* __restrict__ dst, int* __restrict__ deg, int E) {
    int e = blockIdx.x * blockDim.x + threadIdx.x;
    if (e < E) atomicAdd(&deg[dst[e]], 1);
}

__global__ void scan_kernel(const int* __restrict__ deg, int* __restrict__ rs, int N) {
    __shared__ int sm[1024];
    __shared__ int carry_s;
    if (threadIdx.x == 0) carry_s = 0;
    __syncthreads();
    for (int base = 0; base < N; base += 1024) {
        int i = base + threadIdx.x;
        int v = (i < N) ? deg[i] : 0;
        sm[threadIdx.x] = v;
        __syncthreads();
        #pragma unroll
        for (int off = 1; off < 1024; off <<= 1) {
            int t = (threadIdx.x >= off) ? sm[threadIdx.x - off] : 0;
            __syncthreads();
            sm[threadIdx.x] += t;
            __syncthreads();
        }
        int incl = sm[threadIdx.x];
        int carry = carry_s;
        if (i < N) rs[i] = carry + incl - v;
        int total = sm[1023];
        __syncthreads();
        if (threadIdx.x == 0) carry_s = carry + total;
        __syncthreads();
    }
    if (threadIdx.x == 0) rs[N] = carry_s;
}

__global__ void scatter_kernel(const int* __restrict__ src, const int* __restrict__ dst,
                               int* __restrict__ cur, int* __restrict__ csrc, int E) {
    int e = blockIdx.x * blockDim.x + threadIdx.x;
    if (e >= E) return;
    int slot = atomicAdd(&cur[dst[e]], 1);
    csrc[slot] = src[e];
}

// ---------------- fused GAT: softmax + aggregate + ELU, warp per node ----------------
template<int DCH>
__global__ void gat_fused_kernel(const float* __restrict__ H,
                                 const float* __restrict__ es,
                                 const float* __restrict__ ed,
                                 const int* __restrict__ rs,
                                 const int* __restrict__ csrc,
                                 float* __restrict__ out, int ldo, int N) {
    int node = (blockIdx.x * blockDim.x + threadIdx.x) >> 5;
    int lane = threadIdx.x & 31;
    if (node >= N) return;
    int s0 = rs[node], s1 = rs[node + 1];

    float4 acc[DCH];
    #pragma unroll
    for (int c = 0; c < DCH; c++) acc[c] = make_float4(0.f, 0.f, 0.f, 0.f);

    if (s0 < s1) {
        const float edv = ed[node];
        float mx = -CUDART_INF_F;
        for (int i = s0 + lane; i < s1; i += 32) {
            float v = es[csrc[i]] + edv;
            v = v > 0.f ? v : 0.2f * v;
            mx = fmaxf(mx, v);
        }
        #pragma unroll
        for (int o = 16; o; o >>= 1) mx = fmaxf(mx, __shfl_xor_sync(0xffffffffu, mx, o));

        float ssum = 0.f;
        for (int i = s0 + lane; i < s1; i += 32) {
            float v = es[csrc[i]] + edv;
            v = v > 0.f ? v : 0.2f * v;
            ssum += expf(v - mx);
        }
        #pragma unroll
        for (int o = 16; o; o >>= 1) ssum += __shfl_xor_sync(0xffffffffu, ssum, o);
        float inv = 1.f / (ssum + 1e-16f);

        for (int i = s0; i < s1; i++) {
            int s = csrc[i];
            float v = es[s] + edv;
            v = v > 0.f ? v : 0.2f * v;
            float alpha = expf(v - mx) * inv;
            const float4* hrow = (const float4*)(H + (size_t)s * (DCH * 128));
            #pragma unroll
            for (int c = 0; c < DCH; c++) {
                float4 hv = hrow[c * 32 + lane];
                acc[c].x = fmaf(alpha, hv.x, acc[c].x);
                acc[c].y = fmaf(alpha, hv.y, acc[c].y);
                acc[c].z = fmaf(alpha, hv.z, acc[c].z);
                acc[c].w = fmaf(alpha, hv.w, acc[c].w);
            }
        }
    }

    float4* orow = (float4*)(out + (size_t)node * ldo);
    #pragma unroll
    for (int c = 0; c < DCH; c++) {
        float4 v = acc[c];
        v.x = v.x > 0.f ? v.x : expm1f(v.x);
        v.y = v.y > 0.f ? v.y : expm1f(v.y);
        v.z = v.z > 0.f ? v.z : expm1f(v.z);
        v.w = v.w > 0.f ? v.w : expm1f(v.w);
        orow[c * 32 + lane] = v;
    }
}

// ---------------- misc kernels ----------------

__global__ void node_dots_kernel(const float* __restrict__ H,
                                 const float* __restrict__ a_src,
                                 const float* __restrict__ a_dst,
                                 float* __restrict__ es, float* __restrict__ ed,
                                 int N, int D) {
    int warp = (blockIdx.x * blockDim.x + threadIdx.x) >> 5;
    int lane = threadIdx.x & 31;
    if (warp >= N) return;
    const float* row = H + (size_t)warp * D;
    float s1 = 0.f, s2 = 0.f;
    for (int j = lane; j < D; j += 32) {
        float v = row[j];
        s1 += v * a_src[j];
        s2 += v * a_dst[j];
    }
    #pragma unroll
    for (int o = 16; o; o >>= 1) {
        s1 += __shfl_down_sync(0xffffffffu, s1, o);
        s2 += __shfl_down_sync(0xffffffffu, s2, o);
    }
    if (lane == 0) { es[warp] = s1; ed[warp] = s2; }
}

__global__ void gather_rows4_kernel(const float4* __restrict__ in, const int* __restrict__ perm,
                                    float4* __restrict__ out, int N, int Dv) {
    size_t i = (size_t)blockIdx.x * blockDim.x + threadIdx.x;
    if (i >= (size_t)N * Dv) return;
    int r = (int)(i / Dv);
    int c = (int)(i - (size_t)r * Dv);
    out[i] = in[(size_t)perm[r] * Dv + c];
}

__global__ void summary_kernel(const float* __restrict__ h2, float* __restrict__ out, int N) {
    int c = blockIdx.x;
    __shared__ float sm[256];
    float s = 0.f;
    for (int i = threadIdx.x; i < N; i += blockDim.x)
        s += h2[(size_t)i * OUTD + c];
    sm[threadIdx.x] = s;
    __syncthreads();
    for (int o = 128; o; o >>= 1) {
        if (threadIdx.x < o) sm[threadIdx.x] += sm[threadIdx.x + o];
        __syncthreads();
    }
    if (threadIdx.x == 0) {
        float m = sm[0] / (float)N;
        out[c] = 1.f / (1.f + expf(-m));
    }
}

// ---------------- host orchestration ----------------

template<int DCH>
static void run_gat(const float* H,
                    const float* a_src, const float* a_dst,
                    const int* rs, const int* csrc,
                    float* es, float* ed,
                    float* out, int ldo) {
    node_dots_kernel<<<(NN * 32 + 255) / 256, 256>>>(H, a_src, a_dst, es, ed, NN, DCH * 128);
    gat_fused_kernel<DCH><<<(NN * 8 * 32 + 255) / 256, 256>>>(H, es, ed, rs, csrc, out, ldo, NN);
}

extern "C" void kernel_launch(void* const* d_in, const int* in_sizes, int n_in,
                              void* d_out, int out_size) {
    const float* features    = (const float*)d_in[0];
    const float* im_features = (const float*)d_in[1];
    const float* W1x         = (const float*)d_in[2];
    const float* a1x_src     = (const float*)d_in[3];
    const float* a1x_dst     = (const float*)d_in[4];
    const float* W1r         = (const float*)d_in[5];
    const float* a1r_src     = (const float*)d_in[6];
    const float* a1r_dst     = (const float*)d_in[7];
    const float* W2          = (const float*)d_in[8];
    const float* a3_src      = (const float*)d_in[9];
    const float* a3_dst      = (const float*)d_in[10];
    const int*   edge_index  = (const int*)d_in[11];
    const int*   perm        = (const int*)d_in[12];

    const int* src = edge_index;
    const int* dst = edge_index + EE;

    // allow >48KB dynamic smem for both GEMM instantiations (host API, no alloc)
    cudaFuncSetAttribute(tf32_gemm<false>, cudaFuncAttributeMaxDynamicSharedMemorySize, smem_bytes(false));
    cudaFuncSetAttribute(tf32_gemm<true >, cudaFuncAttributeMaxDynamicSharedMemorySize, smem_bytes(true ));

    void* p;
    cudaGetSymbolAddress(&p, g_H1x);  float* H1x  = (float*)p;
    cudaGetSymbolAddress(&p, g_H1r);  float* H1r  = (float*)p;
    cudaGetSymbolAddress(&p, g_Hgx);  float* Hgx  = (float*)p;
    cudaGetSymbolAddress(&p, g_Hgr);  float* Hgr  = (float*)p;
    cudaGetSymbolAddress(&p, g_t);    float* tbuf = (float*)p;
    cudaGetSymbolAddress(&p, g_hdec); float* hdec = (float*)p;
    cudaGetSymbolAddress(&p, g_h3);   float* h3   = (float*)p;
    cudaGetSymbolAddress(&p, g_es);   float* es   = (float*)p;
    cudaGetSymbolAddress(&p, g_ed);   float* ed   = (float*)p;
    cudaGetSymbolAddress(&p, g_deg);  int*   deg  = (int*)p;
    cudaGetSymbolAddress(&p, g_rs);   int*   rs   = (int*)p;
    cudaGetSymbolAddress(&p, g_cur);  int*   cur  = (int*)p;
    cudaGetSymbolAddress(&p, g_csrc); int*   csrc = (int*)p;

    float* out = (float*)d_out;
    const size_t S_h2  = (size_t)NN * OUTD;
    const size_t S_h4x = (size_t)NN * INX;
    const size_t S_h4r = (size_t)NN * INR;
    const size_t passSz = S_h2 + S_h4x + S_h4r;

    // ---- CSR build (once per launch; shared by all 6 GATs) ----
    cudaMemsetAsync(deg, 0, NN * sizeof(int));
    deg_kernel<<<(EE + 255) / 256, 256>>>(dst, deg, EE);
    scan_kernel<<<1, 1024>>>(deg, rs, NN);
    cudaMemcpyAsync(cur, rs, NN * sizeof(int), cudaMemcpyDeviceToDevice);
    scatter_kernel<<<(EE + 255) / 256, 256>>>(src, dst, cur, csrc, EE);

    // Big input GEMMs once; permuted pass reuses rows via gather.
    sgemm(features,    W1x, H1x, NN, NH, INX, INX, NH, NH, false);
    sgemm(im_features, W1r, H1r, NN, NH, INR, INR, NH, NH, false);

    for (int pass = 0; pass < 2; pass++) {
        const float* Hx = H1x;
        const float* Hr = H1r;
        if (pass) {
            size_t n4 = (size_t)NN * (NH / 4);
            gather_rows4_kernel<<<(unsigned)((n4 + 255) / 256), 256>>>((const float4*)H1x, perm, (float4*)Hgx, NN, NH / 4);
            gather_rows4_kernel<<<(unsigned)((n4 + 255) / 256), 256>>>((const float4*)H1r, perm, (float4*)Hgr, NN, NH / 4);
            Hx = Hgx; Hr = Hgr;
        }

        run_gat<2>(Hx, a1x_src, a1x_dst, rs, csrc, es, ed, tbuf,      D2);
        run_gat<2>(Hr, a1r_src, a1r_dst, rs, csrc, es, ed, tbuf + NH, D2);

        float* h2  = out + (size_t)pass * passSz;
        float* h4x = h2 + S_h2;
        float* h4r = h4x + S_h4x;

        sgemm(tbuf, W2, h2, NN, OUTD, D2, D2, OUTD, OUTD, false);
        sgemm(h2, W2, hdec, NN, D2, OUTD, OUTD, OUTD, D2, true);

        run_gat<4>(hdec, a3_src, a3_dst, rs, csrc, es, ed, h3, D2);

        sgemm(h3,      W1x, h4x, NN, INX, NH, D2, NH, INX, true);
        sgemm(h3 + NH, W1r, h4r, NN, INR, NH, D2, NH, INR, true);
    }

    summary_kernel<<<OUTD, 256>>>(out, out + 2 * passSz, NN);
}

// round 9
// speedup vs baseline: 4.4452x; 1.0975x over previous
#include <cuda_runtime.h>
#include <cuda_bf16.h>
#include <cstdint>
#include <cstdio>
#include <math_constants.h>

// Problem shape (fixed by the dataset)
#define NN   30000
#define EE   480000
#define INX  3000
#define INR  2048
#define NH   256
#define OUTD 64
#define D2   (2*NH)   // 512

// ---------------- scratch (device globals; no allocs allowed) ----------------
__device__ float    g_H1x [(size_t)NN*NH];
__device__ float    g_H1r [(size_t)NN*NH];
__device__ float    g_Hgx [(size_t)NN*NH];
__device__ float    g_Hgr [(size_t)NN*NH];
__device__ float    g_t   [(size_t)NN*D2];
__device__ float    g_hdec[(size_t)NN*D2];
__device__ float    g_h3  [(size_t)NN*D2];
__device__ float    g_es  [NN];
__device__ float    g_ed  [NN];
__device__ int      g_deg [NN];
__device__ int      g_rs  [NN + 1];
__device__ int      g_cur [NN];
__device__ int      g_csrc[EE];
// pre-converted (tf32 bit pattern) weights
__device__ float    g_W1xc[(size_t)INX*NH];
__device__ float    g_W1rc[(size_t)INR*NH];
__device__ float    g_W2c [(size_t)D2*OUTD];

// ---------------- TF32 tensor-core GEMM, cp.async 4-stage pipeline ----------------
// C[M,N] = A[M,K] @ B      (TB=false, B is K x N)    [B pre-converted to tf32 bits]
// C[M,N] = A[M,K] @ B^T    (TB=true,  B is N x K)    [B pre-converted to tf32 bits]
#define GBM 128
#define GBN 128
#define GBK 16
#define STAGES 4
#define AS_STRIDE 20           // 16 + 4 pad, conflict-free fragment LDS
#define BS_STRIDE_KN 136       // !TB: [k][n] rows, 128+8 pad
#define BS_STRIDE_NK 20        // TB:  [n][k] rows, like A

#define A_STG (GBM * AS_STRIDE)

__device__ __forceinline__ unsigned f2tf32(float f) {
    unsigned r;
    asm("cvt.rna.tf32.f32 %0, %1;" : "=r"(r) : "f"(f));
    return r;
}

__device__ __forceinline__ void cp_async16(uint32_t saddr, const void* gptr, int src_size) {
    asm volatile("cp.async.cg.shared.global [%0], [%1], 16, %2;\n"
                 :: "r"(saddr), "l"(gptr), "r"(src_size));
}
__device__ __forceinline__ void cp_commit() {
    asm volatile("cp.async.commit_group;\n");
}
template<int NWAIT>
__device__ __forceinline__ void cp_wait() {
    asm volatile("cp.async.wait_group %0;\n" :: "n"(NWAIT));
}

__device__ __forceinline__ void mma_tf32(float c[4],
                                         unsigned a0, unsigned a1, unsigned a2, unsigned a3,
                                         unsigned b0, unsigned b1) {
    asm volatile(
        "mma.sync.aligned.m16n8k8.row.col.f32.tf32.tf32.f32 "
        "{%0,%1,%2,%3}, {%4,%5,%6,%7}, {%8,%9}, {%0,%1,%2,%3};"
        : "+f"(c[0]), "+f"(c[1]), "+f"(c[2]), "+f"(c[3])
        : "r"(a0), "r"(a1), "r"(a2), "r"(a3), "r"(b0), "r"(b1));
}

template<bool TB>
__global__ __launch_bounds__(256)
void tf32_gemm(const float* __restrict__ A, const float* __restrict__ B,
               float* __restrict__ C, int M, int N, int K,
               int lda, int ldb, int ldc) {
    constexpr int B_STG = TB ? (GBN * BS_STRIDE_NK) : (GBK * BS_STRIDE_KN);

    extern __shared__ float smem[];
    float* As = smem;
    float* Bs = smem + STAGES * A_STG;

    const int tid  = threadIdx.x;
    const int lane = tid & 31;
    const int wid  = tid >> 5;
    const int wm   = wid & 3;
    const int wn   = wid >> 2;
    const int bm   = blockIdx.y * GBM;
    const int bn   = blockIdx.x * GBN;
    const int grp  = lane >> 2;
    const int tig  = lane & 3;

    // uniform full-tile predicate: interior tiles skip m/n bounds work entirely
    const bool full = (bm + GBM <= M) && (bn + GBN <= N);

    float acc[2][8][4];
    #pragma unroll
    for (int i = 0; i < 2; i++)
        #pragma unroll
        for (int j = 0; j < 8; j++)
            #pragma unroll
            for (int q = 0; q < 4; q++) acc[i][j][q] = 0.f;

    const int ar  = tid >> 1;               // A row 0..127 (also TB B row)
    const int ah  = (tid & 1) * 2;          // float4 index base {0,2}

    // hoisted per-thread global base pointers (valid row clamp computed once)
    const float* Agbase;
    {
        int m = bm + ar;
        Agbase = A + (size_t)(full ? m : min(m, M - 1)) * lda;
    }
    const bool a_row_ok = full || (bm + ar < M);

    const float* Bgbase_tb = nullptr;  bool b_row_ok = true;
    const float* Bgbase_kn = nullptr;  int  b_kr = 0;   int b_nqb = 0; bool b_n_ok0 = true, b_n_ok1 = true;
    if (TB) {
        int n = bn + ar;
        Bgbase_tb = B + (size_t)(full ? n : min(n, N - 1)) * ldb;
        b_row_ok = full || (bn + ar < N);
    } else {
        b_kr  = tid >> 4;
        b_nqb = (tid & 15) * 2;
        b_n_ok0 = full || (bn + (b_nqb    ) * 4 + 4 <= N);
        b_n_ok1 = full || (bn + (b_nqb + 1) * 4 + 4 <= N);
        Bgbase_kn = B;   // row varies with k each tile
    }

    auto issue_tile = [&](int t, int stage) {
        const int k0 = t * GBK;
        // A tile: [128][16]
        #pragma unroll
        for (int h = 0; h < 2; h++) {
            int q = ah + h;
            int k = k0 + q * 4;
            bool ok = a_row_ok && (k + 4 <= K);
            uint32_t sa = (uint32_t)__cvta_generic_to_shared(
                &As[stage * A_STG + ar * AS_STRIDE + q * 4]);
            cp_async16(sa, Agbase + (ok ? k : 0), ok ? 16 : 0);
        }
        if (!TB) {
            int kr = k0 + b_kr;
            const float* gb = Bgbase_kn + (size_t)min(kr, K - 1) * ldb;
            bool krow = kr < K;
            #pragma unroll
            for (int h = 0; h < 2; h++) {
                int q = b_nqb + h;
                bool ok = krow && (h ? b_n_ok1 : b_n_ok0);
                uint32_t sa = (uint32_t)__cvta_generic_to_shared(
                    &Bs[stage * B_STG + b_kr * BS_STRIDE_KN + q * 4]);
                cp_async16(sa, gb + (ok ? bn + q * 4 : 0), ok ? 16 : 0);
            }
        } else {
            #pragma unroll
            for (int h = 0; h < 2; h++) {
                int q = ah + h;
                int k = k0 + q * 4;
                bool ok = b_row_ok && (k + 4 <= K);
                uint32_t sa = (uint32_t)__cvta_generic_to_shared(
                    &Bs[stage * B_STG + ar * BS_STRIDE_NK + q * 4]);
                cp_async16(sa, Bgbase_tb + (ok ? k : 0), ok ? 16 : 0);
            }
        }
    };

    const int nk = (K + GBK - 1) / GBK;

    #pragma unroll
    for (int s = 0; s < STAGES - 1; s++) {
        if (s < nk) issue_tile(s, s);
        cp_commit();
    }

    for (int t = 0; t < nk; t++) {
        cp_wait<STAGES - 2>();
        __syncthreads();
        const int buf = t % STAGES;
        const float* Ab = &As[buf * A_STG];
        const float* Bb = &Bs[buf * B_STG];

        #pragma unroll
        for (int ks = 0; ks < 2; ks++) {
            const int kof = ks * 8;
            unsigned af[2][4], bf[8][2];
            #pragma unroll
            for (int i = 0; i < 2; i++) {
                int r = wm * 32 + i * 16;
                af[i][0] = f2tf32(Ab[(r + grp    ) * AS_STRIDE + kof + tig    ]);
                af[i][1] = f2tf32(Ab[(r + grp + 8) * AS_STRIDE + kof + tig    ]);
                af[i][2] = f2tf32(Ab[(r + grp    ) * AS_STRIDE + kof + tig + 4]);
                af[i][3] = f2tf32(Ab[(r + grp + 8) * AS_STRIDE + kof + tig + 4]);
            }
            #pragma unroll
            for (int j = 0; j < 8; j++) {
                int c = wn * 64 + j * 8 + grp;
                if (!TB) {
                    bf[j][0] = __float_as_uint(Bb[(kof + tig    ) * BS_STRIDE_KN + c]);
                    bf[j][1] = __float_as_uint(Bb[(kof + tig + 4) * BS_STRIDE_KN + c]);
                } else {
                    bf[j][0] = __float_as_uint(Bb[c * BS_STRIDE_NK + kof + tig    ]);
                    bf[j][1] = __float_as_uint(Bb[c * BS_STRIDE_NK + kof + tig + 4]);
                }
            }
            #pragma unroll
            for (int i = 0; i < 2; i++)
                #pragma unroll
                for (int j = 0; j < 8; j++)
                    mma_tf32(acc[i][j], af[i][0], af[i][1], af[i][2], af[i][3],
                             bf[j][0], bf[j][1]);
        }

        int nt = t + STAGES - 1;
        if (nt < nk) issue_tile(nt, nt % STAGES);
        cp_commit();
    }

    #pragma unroll
    for (int i = 0; i < 2; i++) {
        int r0 = bm + wm * 32 + i * 16 + grp;
        int r1 = r0 + 8;
        #pragma unroll
        for (int j = 0; j < 8; j++) {
            int c = bn + wn * 64 + j * 8 + 2 * tig;
            if (full || r0 < M) {
                if (full || c + 1 < N) *(float2*)&C[(size_t)r0 * ldc + c] = make_float2(acc[i][j][0], acc[i][j][1]);
                else if (c < N) C[(size_t)r0 * ldc + c] = acc[i][j][0];
            }
            if (full || r1 < M) {
                if (full || c + 1 < N) *(float2*)&C[(size_t)r1 * ldc + c] = make_float2(acc[i][j][2], acc[i][j][3]);
                else if (c < N) C[(size_t)r1 * ldc + c] = acc[i][j][2];
            }
        }
    }
}

static int smem_bytes(bool transB) {
    int bstg = transB ? (GBN * BS_STRIDE_NK) : (GBK * BS_STRIDE_KN);
    return (STAGES * A_STG + STAGES * bstg) * 4;
}

static void sgemm(const float* A, const float* B, float* C,
                  int M, int N, int K, int lda, int ldb, int ldc, bool transB) {
    dim3 grid((N + GBN - 1) / GBN, (M + GBM - 1) / GBM);
    if (transB) tf32_gemm<true ><<<grid, 256, smem_bytes(true )>>>(A, B, C, M, N, K, lda, ldb, ldc);
    else        tf32_gemm<false><<<grid, 256, smem_bytes(false)>>>(A, B, C, M, N, K, lda, ldb, ldc);
}

// weight pre-conversion: fp32 -> tf32 bit pattern (stored as float)
__global__ void cvt_tf32_kernel(const float* __restrict__ in, float* __restrict__ out, int n) {
    int i = blockIdx.x * blockDim.x + threadIdx.x;
    if (i < n) out[i] = __uint_as_float(f2tf32(in[i]));
}

// ---------------- CSR build (per launch; graph static across all 6 GATs) ----------------

__global__ void deg_kernel(const int* __restrict__ dst, int* __restrict__ deg, int E) {
    int e = blockIdx.x * blockDim.x + threadIdx.x;
    if (e < E) atomicAdd(&deg[dst[e]], 1);
}

__global__ void scan_kernel(const int* __restrict__ deg, int* __restrict__ rs, int N) {
    __shared__ int sm[1024];
    __shared__ int carry_s;
    if (threadIdx.x == 0) carry_s = 0;
    __syncthreads();
    for (int base = 0; base < N; base += 1024) {
        int i = base + threadIdx.x;
        int v = (i < N) ? deg[i] : 0;
        sm[threadIdx.x] = v;
        __syncthreads();
        #pragma unroll
        for (int off = 1; off < 1024; off <<= 1) {
            int t = (threadIdx.x >= off) ? sm[threadIdx.x - off] : 0;
            __syncthreads();
            sm[threadIdx.x] += t;
            __syncthreads();
        }
        int incl = sm[threadIdx.x];
        int carry = carry_s;
        if (i < N) rs[i] = carry + incl - v;
        int total = sm[1023];
        __syncthreads();
        if (threadIdx.x == 0) carry_s = carry + total;
        __syncthreads();
    }
    if (threadIdx.x == 0) rs[N] = carry_s;
}

__global__ void scatter_kernel(const int* __restrict__ src, const int* __restrict__ dst,
                               int* __restrict__ cur, int* __restrict__ csrc, int E) {
    int e = blockIdx.x * blockDim.x + threadIdx.x;
    if (e >= E) return;
    int slot = atomicAdd(&cur[dst[e]], 1);
    csrc[slot] = src[e];
}

// ---------------- fused GAT: softmax + aggregate + ELU, warp per node ----------------
template<int DCH>
__global__ void gat_fused_kernel(const float* __restrict__ H,
                                 const float* __restrict__ es,
                                 const float* __restrict__ ed,
                                 const int* __restrict__ rs,
                                 const int* __restrict__ csrc,
                                 float* __restrict__ out, int ldo, int N) {
    int node = (blockIdx.x * blockDim.x + threadIdx.x) >> 5;
    int lane = threadIdx.x & 31;
    if (node >= N) return;
    int s0 = rs[node], s1 = rs[node + 1];

    float4 acc[DCH];
    #pragma unroll
    for (int c = 0; c < DCH; c++) acc[c] = make_float4(0.f, 0.f, 0.f, 0.f);

    if (s0 < s1) {
        const float edv = ed[node];
        float mx = -CUDART_INF_F;
        for (int i = s0 + lane; i < s1; i += 32) {
            float v = es[csrc[i]] + edv;
            v = v > 0.f ? v : 0.2f * v;
            mx = fmaxf(mx, v);
        }
        #pragma unroll
        for (int o = 16; o; o >>= 1) mx = fmaxf(mx, __shfl_xor_sync(0xffffffffu, mx, o));

        float ssum = 0.f;
        for (int i = s0 + lane; i < s1; i += 32) {
            float v = es[csrc[i]] + edv;
            v = v > 0.f ? v : 0.2f * v;
            ssum += expf(v - mx);
        }
        #pragma unroll
        for (int o = 16; o; o >>= 1) ssum += __shfl_xor_sync(0xffffffffu, ssum, o);
        float inv = 1.f / (ssum + 1e-16f);

        for (int i = s0; i < s1; i++) {
            int s = csrc[i];
            float v = es[s] + edv;
            v = v > 0.f ? v : 0.2f * v;
            float alpha = expf(v - mx) * inv;
            const float4* hrow = (const float4*)(H + (size_t)s * (DCH * 128));
            #pragma unroll
            for (int c = 0; c < DCH; c++) {
                float4 hv = hrow[c * 32 + lane];
                acc[c].x = fmaf(alpha, hv.x, acc[c].x);
                acc[c].y = fmaf(alpha, hv.y, acc[c].y);
                acc[c].z = fmaf(alpha, hv.z, acc[c].z);
                acc[c].w = fmaf(alpha, hv.w, acc[c].w);
            }
        }
    }

    float4* orow = (float4*)(out + (size_t)node * ldo);
    #pragma unroll
    for (int c = 0; c < DCH; c++) {
        float4 v = acc[c];
        v.x = v.x > 0.f ? v.x : expm1f(v.x);
        v.y = v.y > 0.f ? v.y : expm1f(v.y);
        v.z = v.z > 0.f ? v.z : expm1f(v.z);
        v.w = v.w > 0.f ? v.w : expm1f(v.w);
        orow[c * 32 + lane] = v;
    }
}

// ---------------- misc kernels ----------------

__global__ void node_dots_kernel(const float* __restrict__ H,
                                 const float* __restrict__ a_src,
                                 const float* __restrict__ a_dst,
                                 float* __restrict__ es, float* __restrict__ ed,
                                 int N, int D) {
    int warp = (blockIdx.x * blockDim.x + threadIdx.x) >> 5;
    int lane = threadIdx.x & 31;
    if (warp >= N) return;
    const float* row = H + (size_t)warp * D;
    float s1 = 0.f, s2 = 0.f;
    for (int j = lane; j < D; j += 32) {
        float v = row[j];
        s1 += v * a_src[j];
        s2 += v * a_dst[j];
    }
    #pragma unroll
    for (int o = 16; o; o >>= 1) {
        s1 += __shfl_down_sync(0xffffffffu, s1, o);
        s2 += __shfl_down_sync(0xffffffffu, s2, o);
    }
    if (lane == 0) { es[warp] = s1; ed[warp] = s2; }
}

__global__ void gather_rows4_kernel(const float4* __restrict__ in, const int* __restrict__ perm,
                                    float4* __restrict__ out, int N, int Dv) {
    size_t i = (size_t)blockIdx.x * blockDim.x + threadIdx.x;
    if (i >= (size_t)N * Dv) return;
    int r = (int)(i / Dv);
    int c = (int)(i - (size_t)r * Dv);
    out[i] = in[(size_t)perm[r] * Dv + c];
}

__global__ void summary_kernel(const float* __restrict__ h2, float* __restrict__ out, int N) {
    int c = blockIdx.x;
    __shared__ float sm[256];
    float s = 0.f;
    for (int i = threadIdx.x; i < N; i += blockDim.x)
        s += h2[(size_t)i * OUTD + c];
    sm[threadIdx.x] = s;
    __syncthreads();
    for (int o = 128; o; o >>= 1) {
        if (threadIdx.x < o) sm[threadIdx.x] += sm[threadIdx.x + o];
        __syncthreads();
    }
    if (threadIdx.x == 0) {
        float m = sm[0] / (float)N;
        out[c] = 1.f / (1.f + expf(-m));
    }
}

// ---------------- host orchestration ----------------

template<int DCH>
static void run_gat(const float* H,
                    const float* a_src, const float* a_dst,
                    const int* rs, const int* csrc,
                    float* es, float* ed,
                    float* out, int ldo) {
    node_dots_kernel<<<(NN * 32 + 255) / 256, 256>>>(H, a_src, a_dst, es, ed, NN, DCH * 128);
    gat_fused_kernel<DCH><<<(NN * 8 * 32 + 255) / 256, 256>>>(H, es, ed, rs, csrc, out, ldo, NN);
}

extern "C" void kernel_launch(void* const* d_in, const int* in_sizes, int n_in,
                              void* d_out, int out_size) {
    const float* features    = (const float*)d_in[0];
    const float* im_features = (const float*)d_in[1];
    const float* W1x         = (const float*)d_in[2];
    const float* a1x_src     = (const float*)d_in[3];
    const float* a1x_dst     = (const float*)d_in[4];
    const float* W1r         = (const float*)d_in[5];
    const float* a1r_src     = (const float*)d_in[6];
    const float* a1r_dst     = (const float*)d_in[7];
    const float* W2          = (const float*)d_in[8];
    const float* a3_src      = (const float*)d_in[9];
    const float* a3_dst      = (const float*)d_in[10];
    const int*   edge_index  = (const int*)d_in[11];
    const int*   perm        = (const int*)d_in[12];

    const int* src = edge_index;
    const int* dst = edge_index + EE;

    cudaFuncSetAttribute(tf32_gemm<false>, cudaFuncAttributeMaxDynamicSharedMemorySize, smem_bytes(false));
    cudaFuncSetAttribute(tf32_gemm<true >, cudaFuncAttributeMaxDynamicSharedMemorySize, smem_bytes(true ));

    void* p;
    cudaGetSymbolAddress(&p, g_H1x);  float* H1x  = (float*)p;
    cudaGetSymbolAddress(&p, g_H1r);  float* H1r  = (float*)p;
    cudaGetSymbolAddress(&p, g_Hgx);  float* Hgx  = (float*)p;
    cudaGetSymbolAddress(&p, g_Hgr);  float* Hgr  = (float*)p;
    cudaGetSymbolAddress(&p, g_t);    float* tbuf = (float*)p;
    cudaGetSymbolAddress(&p, g_hdec); float* hdec = (float*)p;
    cudaGetSymbolAddress(&p, g_h3);   float* h3   = (float*)p;
    cudaGetSymbolAddress(&p, g_es);   float* es   = (float*)p;
    cudaGetSymbolAddress(&p, g_ed);   float* ed   = (float*)p;
    cudaGetSymbolAddress(&p, g_deg);  int*   deg  = (int*)p;
    cudaGetSymbolAddress(&p, g_rs);   int*   rs   = (int*)p;
    cudaGetSymbolAddress(&p, g_cur);  int*   cur  = (int*)p;
    cudaGetSymbolAddress(&p, g_csrc); int*   csrc = (int*)p;
    cudaGetSymbolAddress(&p, g_W1xc); float* W1xc = (float*)p;
    cudaGetSymbolAddress(&p, g_W1rc); float* W1rc = (float*)p;
    cudaGetSymbolAddress(&p, g_W2c);  float* W2c  = (float*)p;

    float* out = (float*)d_out;
    const size_t S_h2  = (size_t)NN * OUTD;
    const size_t S_h4x = (size_t)NN * INX;
    const size_t S_h4r = (size_t)NN * INR;
    const size_t passSz = S_h2 + S_h4x + S_h4r;

    // ---- weight pre-conversion to tf32 bits (once per launch) ----
    cvt_tf32_kernel<<<(INX * NH + 255) / 256, 256>>>(W1x, W1xc, INX * NH);
    cvt_tf32_kernel<<<(INR * NH + 255) / 256, 256>>>(W1r, W1rc, INR * NH);
    cvt_tf32_kernel<<<(D2 * OUTD + 255) / 256, 256>>>(W2,  W2c,  D2 * OUTD);

    // ---- CSR build (once per launch; shared by all 6 GATs) ----
    cudaMemsetAsync(deg, 0, NN * sizeof(int));
    deg_kernel<<<(EE + 255) / 256, 256>>>(dst, deg, EE);
    scan_kernel<<<1, 1024>>>(deg, rs, NN);
    cudaMemcpyAsync(cur, rs, NN * sizeof(int), cudaMemcpyDeviceToDevice);
    scatter_kernel<<<(EE + 255) / 256, 256>>>(src, dst, cur, csrc, EE);

    // Big input GEMMs once; permuted pass reuses rows via gather.
    sgemm(features,    W1xc, H1x, NN, NH, INX, INX, NH, NH, false);
    sgemm(im_features, W1rc, H1r, NN, NH, INR, INR, NH, NH, false);

    for (int pass = 0; pass < 2; pass++) {
        const float* Hx = H1x;
        const float* Hr = H1r;
        if (pass) {
            size_t n4 = (size_t)NN * (NH / 4);
            gather_rows4_kernel<<<(unsigned)((n4 + 255) / 256), 256>>>((const float4*)H1x, perm, (float4*)Hgx, NN, NH / 4);
            gather_rows4_kernel<<<(unsigned)((n4 + 255) / 256), 256>>>((const float4*)H1r, perm, (float4*)Hgr, NN, NH / 4);
            Hx = Hgx; Hr = Hgr;
        }

        run_gat<2>(Hx, a1x_src, a1x_dst, rs, csrc, es, ed, tbuf,      D2);
        run_gat<2>(Hr, a1r_src, a1r_dst, rs, csrc, es, ed, tbuf + NH, D2);

        float* h2  = out + (size_t)pass * passSz;
        float* h4x = h2 + S_h2;
        float* h4r = h4x + S_h4x;

        sgemm(tbuf, W2c, h2, NN, OUTD, D2, D2, OUTD, OUTD, false);
        sgemm(h2, W2c, hdec, NN, D2, OUTD, OUTD, OUTD, D2, true);

        run_gat<4>(hdec, a3_src, a3_dst, rs, csrc, es, ed, h3, D2);

        sgemm(h3,      W1xc, h4x, NN, INX, NH, D2, NH, INX, true);
        sgemm(h3 + NH, W1rc, h4r, NN, INR, NH, D2, NH, INR, true);
    }

    summary_kernel<<<OUTD, 256>>>(out, out + 2 * passSz, NN);
}

// round 13
// speedup vs baseline: 4.6777x; 1.0523x over previous
#include <cuda_runtime.h>
#include <cuda_bf16.h>
#include <cstdint>
#include <cstdio>
#include <math_constants.h>

// Problem shape (fixed by the dataset)
#define NN   30000
#define EE   480000
#define INX  3000
#define INR  2048
#define NH   256
#define OUTD 64
#define D2   (2*NH)   // 512

// ---------------- scratch (device globals; no allocs allowed) ----------------
__device__ float    g_H1x [(size_t)NN*NH];
__device__ float    g_H1r [(size_t)NN*NH];
__device__ float    g_Hgx [(size_t)NN*NH];
__device__ float    g_Hgr [(size_t)NN*NH];
__device__ float    g_t   [(size_t)NN*D2];
__device__ float    g_hdec[(size_t)NN*D2];
__device__ float    g_h3  [(size_t)NN*D2];
__device__ float    g_es  [NN];
__device__ float    g_ed  [NN];
__device__ int      g_deg [NN];
__device__ int      g_rs  [NN + 1];
__device__ int      g_cur [NN];
__device__ int      g_csrc[EE];
// pre-converted (tf32 bit pattern) weights, [N][K] row-major for each GEMM use
__device__ float    g_W1xc[(size_t)INX*NH];   // [3000][256]  (B for h4x)
__device__ float    g_W1rc[(size_t)INR*NH];   // [2048][256]  (B for h4r)
__device__ float    g_W2c [(size_t)D2*OUTD];  // [512][64]    (B for hdec)
__device__ float    g_W1xt[(size_t)NH*INX];   // [256][3000]  (B for features GEMM)
__device__ float    g_W1rt[(size_t)NH*INR];   // [256][2048]  (B for im GEMM)
__device__ float    g_W2t [(size_t)OUTD*D2];  // [64][512]    (B for h2 GEMM)

// ---------------- unified TF32 GEMM: C[M,N] = A[M,K] @ Bt^T ----------------
// A: fp32 [M][K] (lda).  Bt: tf32-bit [N][K] (ldb=K).  C: fp32 [M][N] (ldc=N).
#define GBM 128
#define GBN 128
#define GBK 16
#define STAGES 4
#define AS_STRIDE 20           // 16 + 4 pad (floats); 80B rows, ldmatrix conflict-free
#define BS_STRIDE 20

#define A_STG (GBM * AS_STRIDE)
#define B_STG (GBN * BS_STRIDE)

__device__ __forceinline__ unsigned f2tf32(float f) {
    unsigned r;
    asm("cvt.rna.tf32.f32 %0, %1;" : "=r"(r) : "f"(f));
    return r;
}

__device__ __forceinline__ void cp_async16(uint32_t saddr, const void* gptr, int src_size) {
    asm volatile("cp.async.cg.shared.global [%0], [%1], 16, %2;\n"
                 :: "r"(saddr), "l"(gptr), "r"(src_size));
}
__device__ __forceinline__ void cp_commit() {
    asm volatile("cp.async.commit_group;\n");
}
template<int NWAIT>
__device__ __forceinline__ void cp_wait() {
    asm volatile("cp.async.wait_group %0;\n" :: "n"(NWAIT));
}

__device__ __forceinline__ void ldsm_x4(unsigned r[4], uint32_t saddr) {
    asm volatile("ldmatrix.sync.aligned.m8n8.x4.shared.b16 {%0,%1,%2,%3}, [%4];"
                 : "=r"(r[0]), "=r"(r[1]), "=r"(r[2]), "=r"(r[3]) : "r"(saddr));
}

__device__ __forceinline__ void mma_tf32(float c[4],
                                         unsigned a0, unsigned a1, unsigned a2, unsigned a3,
                                         unsigned b0, unsigned b1) {
    asm volatile(
        "mma.sync.aligned.m16n8k8.row.col.f32.tf32.tf32.f32 "
        "{%0,%1,%2,%3}, {%4,%5,%6,%7}, {%8,%9}, {%0,%1,%2,%3};"
        : "+f"(c[0]), "+f"(c[1]), "+f"(c[2]), "+f"(c[3])
        : "r"(a0), "r"(a1), "r"(a2), "r"(a3), "r"(b0), "r"(b1));
}

__global__ __launch_bounds__(256)
void tf32_gemm(const float* __restrict__ A, const float* __restrict__ Bt,
               float* __restrict__ C, int M, int N, int K,
               int lda, int ldb, int ldc) {
    extern __shared__ float smem[];
    float* As = smem;
    float* Bs = smem + STAGES * A_STG;

    const int tid  = threadIdx.x;
    const int lane = tid & 31;
    const int wid  = tid >> 5;
    const int wm   = wid & 3;
    const int wn   = wid >> 2;
    const int bm   = blockIdx.y * GBM;
    const int bn   = blockIdx.x * GBN;
    const int grp  = lane >> 2;
    const int tig  = lane & 3;

    const bool full = (bm + GBM <= M) && (bn + GBN <= N);

    float acc[2][8][4];
    #pragma unroll
    for (int i = 0; i < 2; i++)
        #pragma unroll
        for (int j = 0; j < 8; j++)
            #pragma unroll
            for (int q = 0; q < 4; q++) acc[i][j][q] = 0.f;

    // ---- staging maps (A and B identical: 128 rows x 16 k, 2x16B per thread)
    const int ar  = tid >> 1;
    const int ah  = (tid & 1) * 2;

    const float* Agbase;
    {
        int m = bm + ar;
        Agbase = A + (size_t)(full ? m : min(m, M - 1)) * lda;
    }
    const bool a_row_ok = full || (bm + ar < M);

    const float* Bgbase;
    {
        int n = bn + ar;
        Bgbase = Bt + (size_t)(full ? n : min(n, N - 1)) * ldb;
    }
    const bool b_row_ok = full || (bn + ar < N);

    auto issue_tile = [&](int t, int stage) {
        const int k0 = t * GBK;
        #pragma unroll
        for (int h = 0; h < 2; h++) {
            int q = ah + h;
            int k = k0 + q * 4;
            bool ok = a_row_ok && (k + 4 <= K);
            uint32_t sa = (uint32_t)__cvta_generic_to_shared(
                &As[stage * A_STG + ar * AS_STRIDE + q * 4]);
            cp_async16(sa, Agbase + (ok ? k : 0), ok ? 16 : 0);
        }
        #pragma unroll
        for (int h = 0; h < 2; h++) {
            int q = ah + h;
            int k = k0 + q * 4;
            bool ok = b_row_ok && (k + 4 <= K);
            uint32_t sa = (uint32_t)__cvta_generic_to_shared(
                &Bs[stage * B_STG + ar * BS_STRIDE + q * 4]);
            cp_async16(sa, Bgbase + (ok ? k : 0), ok ? 16 : 0);
        }
    };

    // ---- ldmatrix per-thread fragment addresses (byte offsets within a stage)
    // A matrices 0..3: rows (lane&15), col 4*(lane>>4)
    const uint32_t as_base = (uint32_t)__cvta_generic_to_shared(As);
    const uint32_t bs_base = (uint32_t)__cvta_generic_to_shared(Bs);
    const uint32_t a_frag = ((wm * 32 + (lane & 15)) * AS_STRIDE + ((lane >> 4) << 2)) * 4;
    // B matrices 0..3: rows (lane&7) + 8*(lane>>4), col 4*((lane&8)>>3)
    const uint32_t b_frag = ((wn * 64 + (lane & 7) + ((lane >> 4) << 3)) * BS_STRIDE
                             + ((lane & 8) >> 1)) * 4;

    const int nk = (K + GBK - 1) / GBK;

    #pragma unroll
    for (int s = 0; s < STAGES - 1; s++) {
        if (s < nk) issue_tile(s, s);
        cp_commit();
    }

    for (int t = 0; t < nk; t++) {
        cp_wait<STAGES - 2>();
        __syncthreads();
        const int buf = t % STAGES;
        const uint32_t abuf = as_base + buf * (A_STG * 4) + a_frag;
        const uint32_t bbuf = bs_base + buf * (B_STG * 4) + b_frag;

        #pragma unroll
        for (int ks = 0; ks < 2; ks++) {
            const uint32_t kofb = ks * 32;   // 8 floats
            unsigned af[2][4];
            #pragma unroll
            for (int i = 0; i < 2; i++) {
                ldsm_x4(af[i], abuf + i * (16 * AS_STRIDE * 4) + kofb);
                af[i][0] = f2tf32(__uint_as_float(af[i][0]));
                af[i][1] = f2tf32(__uint_as_float(af[i][1]));
                af[i][2] = f2tf32(__uint_as_float(af[i][2]));
                af[i][3] = f2tf32(__uint_as_float(af[i][3]));
            }
            #pragma unroll
            for (int jp = 0; jp < 4; jp++) {
                unsigned bq[4];
                ldsm_x4(bq, bbuf + jp * (16 * BS_STRIDE * 4) + kofb);
                #pragma unroll
                for (int i = 0; i < 2; i++) {
                    mma_tf32(acc[i][2 * jp    ], af[i][0], af[i][1], af[i][2], af[i][3], bq[0], bq[1]);
                    mma_tf32(acc[i][2 * jp + 1], af[i][0], af[i][1], af[i][2], af[i][3], bq[2], bq[3]);
                }
            }
        }

        int nt = t + STAGES - 1;
        if (nt < nk) issue_tile(nt, nt % STAGES);
        cp_commit();
    }

    #pragma unroll
    for (int i = 0; i < 2; i++) {
        int r0 = bm + wm * 32 + i * 16 + grp;
        int r1 = r0 + 8;
        #pragma unroll
        for (int j = 0; j < 8; j++) {
            int c = bn + wn * 64 + j * 8 + 2 * tig;
            if (full || r0 < M) {
                if (full || c + 1 < N) *(float2*)&C[(size_t)r0 * ldc + c] = make_float2(acc[i][j][0], acc[i][j][1]);
                else if (c < N) C[(size_t)r0 * ldc + c] = acc[i][j][0];
            }
            if (full || r1 < M) {
                if (full || c + 1 < N) *(float2*)&C[(size_t)r1 * ldc + c] = make_float2(acc[i][j][2], acc[i][j][3]);
                else if (c < N) C[(size_t)r1 * ldc + c] = acc[i][j][2];
            }
        }
    }
}

static int smem_bytes() { return (STAGES * (A_STG + B_STG)) * 4; }

static void sgemm(const float* A, const float* Bt, float* C,
                  int M, int N, int K, int lda) {
    dim3 grid((N + GBN - 1) / GBN, (M + GBM - 1) / GBM);
    tf32_gemm<<<grid, 256, smem_bytes()>>>(A, Bt, C, M, N, K, lda, K, N);
}

// weight pre-conversion: fp32 -> tf32 bit pattern
__global__ void cvt_tf32_kernel(const float* __restrict__ in, float* __restrict__ out, int n) {
    int i = blockIdx.x * blockDim.x + threadIdx.x;
    if (i < n) out[i] = __uint_as_float(f2tf32(in[i]));
}

// transpose + convert: in [R][Cc] -> out [Cc][R] (tf32 bits)
__global__ void transpose_cvt_kernel(const float* __restrict__ in, float* __restrict__ out,
                                     int R, int Cc) {
    __shared__ float tile[32][33];
    int c = blockIdx.x * 32 + threadIdx.x;
    int r0 = blockIdx.y * 32;
    #pragma unroll
    for (int dy = 0; dy < 32; dy += 8) {
        int r = r0 + threadIdx.y + dy;
        if (r < R && c < Cc) tile[threadIdx.y + dy][threadIdx.x] = in[(size_t)r * Cc + c];
    }
    __syncthreads();
    int oc = r0 + threadIdx.x;                 // output col (= input row)
    #pragma unroll
    for (int dy = 0; dy < 32; dy += 8) {
        int orow = blockIdx.x * 32 + threadIdx.y + dy;   // output row (= input col)
        if (orow < Cc && oc < R)
            out[(size_t)orow * R + oc] = __uint_as_float(f2tf32(tile[threadIdx.x][threadIdx.y + dy]));
    }
}

// ---------------- CSR build (per launch; graph static across all 6 GATs) ----------------

__global__ void deg_kernel(const int* __restrict__ dst, int* __restrict__ deg, int E) {
    int e = blockIdx.x * blockDim.x + threadIdx.x;
    if (e < E) atomicAdd(&deg[dst[e]], 1);
}

__global__ void scan_kernel(const int* __restrict__ deg, int* __restrict__ rs, int N) {
    __shared__ int sm[1024];
    __shared__ int carry_s;
    if (threadIdx.x == 0) carry_s = 0;
    __syncthreads();
    for (int base = 0; base < N; base += 1024) {
        int i = base + threadIdx.x;
        int v = (i < N) ? deg[i] : 0;
        sm[threadIdx.x] = v;
        __syncthreads();
        #pragma unroll
        for (int off = 1; off < 1024; off <<= 1) {
            int t = (threadIdx.x >= off) ? sm[threadIdx.x - off] : 0;
            __syncthreads();
            sm[threadIdx.x] += t;
            __syncthreads();
        }
        int incl = sm[threadIdx.x];
        int carry = carry_s;
        if (i < N) rs[i] = carry + incl - v;
        int total = sm[1023];
        __syncthreads();
        if (threadIdx.x == 0) carry_s = carry + total;
        __syncthreads();
    }
    if (threadIdx.x == 0) rs[N] = carry_s;
}

__global__ void scatter_kernel(const int* __restrict__ src, const int* __restrict__ dst,
                               int* __restrict__ cur, int* __restrict__ csrc, int E) {
    int e = blockIdx.x * blockDim.x + threadIdx.x;
    if (e >= E) return;
    int slot = atomicAdd(&cur[dst[e]], 1);
    csrc[slot] = src[e];
}

// ---------------- fused GAT: softmax + aggregate + ELU, warp per node ----------------
template<int DCH>
__global__ void gat_fused_kernel(const float* __restrict__ H,
                                 const float* __restrict__ es,
                                 const float* __restrict__ ed,
                                 const int* __restrict__ rs,
                                 const int* __restrict__ csrc,
                                 float* __restrict__ out, int ldo, int N) {
    int node = (blockIdx.x * blockDim.x + threadIdx.x) >> 5;
    int lane = threadIdx.x & 31;
    if (node >= N) return;
    int s0 = rs[node], s1 = rs[node + 1];

    float4 acc[DCH];
    #pragma unroll
    for (int c = 0; c < DCH; c++) acc[c] = make_float4(0.f, 0.f, 0.f, 0.f);

    if (s0 < s1) {
        const float edv = ed[node];
        float mx = -CUDART_INF_F;
        for (int i = s0 + lane; i < s1; i += 32) {
            float v = es[csrc[i]] + edv;
            v = v > 0.f ? v : 0.2f * v;
            mx = fmaxf(mx, v);
        }
        #pragma unroll
        for (int o = 16; o; o >>= 1) mx = fmaxf(mx, __shfl_xor_sync(0xffffffffu, mx, o));

        float ssum = 0.f;
        for (int i = s0 + lane; i < s1; i += 32) {
            float v = es[csrc[i]] + edv;
            v = v > 0.f ? v : 0.2f * v;
            ssum += expf(v - mx);
        }
        #pragma unroll
        for (int o = 16; o; o >>= 1) ssum += __shfl_xor_sync(0xffffffffu, ssum, o);
        float inv = 1.f / (ssum + 1e-16f);

        for (int i = s0; i < s1; i++) {
            int s = csrc[i];
            float v = es[s] + edv;
            v = v > 0.f ? v : 0.2f * v;
            float alpha = expf(v - mx) * inv;
            const float4* hrow = (const float4*)(H + (size_t)s * (DCH * 128));
            #pragma unroll
            for (int c = 0; c < DCH; c++) {
                float4 hv = hrow[c * 32 + lane];
                acc[c].x = fmaf(alpha, hv.x, acc[c].x);
                acc[c].y = fmaf(alpha, hv.y, acc[c].y);
                acc[c].z = fmaf(alpha, hv.z, acc[c].z);
                acc[c].w = fmaf(alpha, hv.w, acc[c].w);
            }
        }
    }

    float4* orow = (float4*)(out + (size_t)node * ldo);
    #pragma unroll
    for (int c = 0; c < DCH; c++) {
        float4 v = acc[c];
        v.x = v.x > 0.f ? v.x : expm1f(v.x);
        v.y = v.y > 0.f ? v.y : expm1f(v.y);
        v.z = v.z > 0.f ? v.z : expm1f(v.z);
        v.w = v.w > 0.f ? v.w : expm1f(v.w);
        orow[c * 32 + lane] = v;
    }
}

// ---------------- misc kernels ----------------

__global__ void node_dots_kernel(const float* __restrict__ H,
                                 const float* __restrict__ a_src,
                                 const float* __restrict__ a_dst,
                                 float* __restrict__ es, float* __restrict__ ed,
                                 int N, int D) {
    int warp = (blockIdx.x * blockDim.x + threadIdx.x) >> 5;
    int lane = threadIdx.x & 31;
    if (warp >= N) return;
    const float* row = H + (size_t)warp * D;
    float s1 = 0.f, s2 = 0.f;
    for (int j = lane; j < D; j += 32) {
        float v = row[j];
        s1 += v * a_src[j];
        s2 += v * a_dst[j];
    }
    #pragma unroll
    for (int o = 16; o; o >>= 1) {
        s1 += __shfl_down_sync(0xffffffffu, s1, o);
        s2 += __shfl_down_sync(0xffffffffu, s2, o);
    }
    if (lane == 0) { es[warp] = s1; ed[warp] = s2; }
}

__global__ void gather_rows4_kernel(const float4* __restrict__ in, const int* __restrict__ perm,
                                    float4* __restrict__ out, int N, int Dv) {
    size_t i = (size_t)blockIdx.x * blockDim.x + threadIdx.x;
    if (i >= (size_t)N * Dv) return;
    int r = (int)(i / Dv);
    int c = (int)(i - (size_t)r * Dv);
    out[i] = in[(size_t)perm[r] * Dv + c];
}

__global__ void summary_kernel(const float* __restrict__ h2, float* __restrict__ out, int N) {
    int c = blockIdx.x;
    __shared__ float sm[256];
    float s = 0.f;
    for (int i = threadIdx.x; i < N; i += blockDim.x)
        s += h2[(size_t)i * OUTD + c];
    sm[threadIdx.x] = s;
    __syncthreads();
    for (int o = 128; o; o >>= 1) {
        if (threadIdx.x < o) sm[threadIdx.x] += sm[threadIdx.x + o];
        __syncthreads();
    }
    if (threadIdx.x == 0) {
        float m = sm[0] / (float)N;
        out[c] = 1.f / (1.f + expf(-m));
    }
}

// ---------------- host orchestration ----------------

template<int DCH>
static void run_gat(const float* H,
                    const float* a_src, const float* a_dst,
                    const int* rs, const int* csrc,
                    float* es, float* ed,
                    float* out, int ldo) {
    node_dots_kernel<<<(NN * 32 + 255) / 256, 256>>>(H, a_src, a_dst, es, ed, NN, DCH * 128);
    gat_fused_kernel<DCH><<<(NN * 8 * 32 + 255) / 256, 256>>>(H, es, ed, rs, csrc, out, ldo, NN);
}

extern "C" void kernel_launch(void* const* d_in, const int* in_sizes, int n_in,
                              void* d_out, int out_size) {
    const float* features    = (const float*)d_in[0];
    const float* im_features = (const float*)d_in[1];
    const float* W1x         = (const float*)d_in[2];
    const float* a1x_src     = (const float*)d_in[3];
    const float* a1x_dst     = (const float*)d_in[4];
    const float* W1r         = (const float*)d_in[5];
    const float* a1r_src     = (const float*)d_in[6];
    const float* a1r_dst     = (const float*)d_in[7];
    const float* W2          = (const float*)d_in[8];
    const float* a3_src      = (const float*)d_in[9];
    const float* a3_dst      = (const float*)d_in[10];
    const int*   edge_index  = (const int*)d_in[11];
    const int*   perm        = (const int*)d_in[12];

    const int* src = edge_index;
    const int* dst = edge_index + EE;

    cudaFuncSetAttribute(tf32_gemm, cudaFuncAttributeMaxDynamicSharedMemorySize, smem_bytes());

    void* p;
    cudaGetSymbolAddress(&p, g_H1x);  float* H1x  = (float*)p;
    cudaGetSymbolAddress(&p, g_H1r);  float* H1r  = (float*)p;
    cudaGetSymbolAddress(&p, g_Hgx);  float* Hgx  = (float*)p;
    cudaGetSymbolAddress(&p, g_Hgr);  float* Hgr  = (float*)p;
    cudaGetSymbolAddress(&p, g_t);    float* tbuf = (float*)p;
    cudaGetSymbolAddress(&p, g_hdec); float* hdec = (float*)p;
    cudaGetSymbolAddress(&p, g_h3);   float* h3   = (float*)p;
    cudaGetSymbolAddress(&p, g_es);   float* es   = (float*)p;
    cudaGetSymbolAddress(&p, g_ed);   float* ed   = (float*)p;
    cudaGetSymbolAddress(&p, g_deg);  int*   deg  = (int*)p;
    cudaGetSymbolAddress(&p, g_rs);   int*   rs   = (int*)p;
    cudaGetSymbolAddress(&p, g_cur);  int*   cur  = (int*)p;
    cudaGetSymbolAddress(&p, g_csrc); int*   csrc = (int*)p;
    cudaGetSymbolAddress(&p, g_W1xc); float* W1xc = (float*)p;
    cudaGetSymbolAddress(&p, g_W1rc); float* W1rc = (float*)p;
    cudaGetSymbolAddress(&p, g_W2c);  float* W2c  = (float*)p;
    cudaGetSymbolAddress(&p, g_W1xt); float* W1xt = (float*)p;
    cudaGetSymbolAddress(&p, g_W1rt); float* W1rt = (float*)p;
    cudaGetSymbolAddress(&p, g_W2t);  float* W2t  = (float*)p;

    float* out = (float*)d_out;
    const size_t S_h2  = (size_t)NN * OUTD;
    const size_t S_h4x = (size_t)NN * INX;
    const size_t S_h4r = (size_t)NN * INR;
    const size_t passSz = S_h2 + S_h4x + S_h4r;

    // ---- weight prep: converted copies + converted-transposed copies ----
    cvt_tf32_kernel<<<(INX * NH + 255) / 256, 256>>>(W1x, W1xc, INX * NH);
    cvt_tf32_kernel<<<(INR * NH + 255) / 256, 256>>>(W1r, W1rc, INR * NH);
    cvt_tf32_kernel<<<(D2 * OUTD + 255) / 256, 256>>>(W2,  W2c,  D2 * OUTD);
    {
        dim3 blk(32, 8);
        dim3 g1((NH + 31) / 32, (INX + 31) / 32);
        transpose_cvt_kernel<<<g1, blk>>>(W1x, W1xt, INX, NH);     // [3000][256] -> [256][3000]
        dim3 g2((NH + 31) / 32, (INR + 31) / 32);
        transpose_cvt_kernel<<<g2, blk>>>(W1r, W1rt, INR, NH);     // [2048][256] -> [256][2048]
        dim3 g3((OUTD + 31) / 32, (D2 + 31) / 32);
        transpose_cvt_kernel<<<g3, blk>>>(W2, W2t, D2, OUTD);      // [512][64] -> [64][512]
    }

    // ---- CSR build (once per launch; shared by all 6 GATs) ----
    cudaMemsetAsync(deg, 0, NN * sizeof(int));
    deg_kernel<<<(EE + 255) / 256, 256>>>(dst, deg, EE);
    scan_kernel<<<1, 1024>>>(deg, rs, NN);
    cudaMemcpyAsync(cur, rs, NN * sizeof(int), cudaMemcpyDeviceToDevice);
    scatter_kernel<<<(EE + 255) / 256, 256>>>(src, dst, cur, csrc, EE);

    // Big input GEMMs once; permuted pass reuses rows via gather.
    sgemm(features,    W1xt, H1x, NN, NH, INX, INX);
    sgemm(im_features, W1rt, H1r, NN, NH, INR, INR);

    for (int pass = 0; pass < 2; pass++) {
        const float* Hx = H1x;
        const float* Hr = H1r;
        if (pass) {
            size_t n4 = (size_t)NN * (NH / 4);
            gather_rows4_kernel<<<(unsigned)((n4 + 255) / 256), 256>>>((const float4*)H1x, perm, (float4*)Hgx, NN, NH / 4);
            gather_rows4_kernel<<<(unsigned)((n4 + 255) / 256), 256>>>((const float4*)H1r, perm, (float4*)Hgr, NN, NH / 4);
            Hx = Hgx; Hr = Hgr;
        }

        run_gat<2>(Hx, a1x_src, a1x_dst, rs, csrc, es, ed, tbuf,      D2);
        run_gat<2>(Hr, a1r_src, a1r_dst, rs, csrc, es, ed, tbuf + NH, D2);

        float* h2  = out + (size_t)pass * passSz;
        float* h4x = h2 + S_h2;
        float* h4r = h4x + S_h4x;

        sgemm(tbuf, W2t, h2,  NN, OUTD, D2,  D2);
        sgemm(h2,   W2c, hdec, NN, D2,  OUTD, OUTD);

        run_gat<4>(hdec, a3_src, a3_dst, rs, csrc, es, ed, h3, D2);

        sgemm(h3,      W1xc, h4x, NN, INX, NH, D2);
        sgemm(h3 + NH, W1rc, h4r, NN, INR, NH, D2);
    }

    summary_kernel<<<OUTD, 256>>>(out, out + 2 * passSz, NN);
}